// round 12
// baseline (speedup 1.0000x reference)
#include <cuda_runtime.h>
#include <cuda_fp16.h>
#include <cstdint>

#define SEQ 512
#define BATCH 256
#define HID 256
#define N4 1024
#define GM_M (SEQ * BATCH)                           // 131072 rows
#define OUT_SEQ_ELEMS ((size_t)SEQ * BATCH * HID)    // 33554432

// scratch
__device__ float g_xw[(size_t)SEQ * BATCH * N4];                 // 512 MB

// A fragments of X (hi/lo fp16 planes): [mt 8192][ks 16][lane 32][reg 4] uint32
__device__ uint32_t g_afhi[(size_t)8192 * 16 * 32 * 4];          // 64 MB
__device__ uint32_t g_aflo[(size_t)8192 * 16 * 32 * 4];          // 64 MB
// B fragments of Wx (single fp16 plane): [nf 128][ks 16][lane 32][reg 2]
__device__ uint32_t g_wf[128 * 16 * 32 * 2];                     // 512 KB

// h fragment buffers: [parity][bg][ (ks*32 + lane)*4 + reg ] uint32 (2 fp16)
#define FRAG_WORDS (16 * 32 * 4)
__device__ uint32_t g_hfhi[2][16][FRAG_WORDS];
__device__ uint32_t g_hflo[2][16][FRAG_WORDS];

// ---------------------------------------------------------------------------
// helpers
// ---------------------------------------------------------------------------
__device__ __forceinline__ float sigmoidf_(float x) {
    return __fdividef(1.0f, 1.0f + __expf(-x));
}
__device__ __forceinline__ float tanhf_fast(float x) {
    return 2.0f * sigmoidf_(2.0f * x) - 1.0f;
}
__device__ __forceinline__ uint32_t packh2(__half a, __half b) {
    return (uint32_t)__half_as_ushort(a) | ((uint32_t)__half_as_ushort(b) << 16);
}
__device__ __forceinline__ uint32_t pack_hi2(float a, float b) {
    return packh2(__float2half(a), __float2half(b));
}
__device__ __forceinline__ uint32_t pack_lo2(float a, float b) {
    __half ha = __float2half(a), hb = __float2half(b);
    return packh2(__float2half(a - __half2float(ha)),
                  __float2half(b - __half2float(hb)));
}

// legacy tensor-core mma fp16 (compute_80 PTX — compiles under compute_103)
__device__ __forceinline__ void mmaf16(float* c, const uint32_t* a, const uint32_t* b) {
    asm volatile(
        "mma.sync.aligned.m16n8k16.row.col.f32.f16.f16.f32 "
        "{%0,%1,%2,%3}, {%4,%5,%6,%7}, {%8,%9}, {%0,%1,%2,%3};"
        : "+f"(c[0]), "+f"(c[1]), "+f"(c[2]), "+f"(c[3])
        : "r"(a[0]), "r"(a[1]), "r"(a[2]), "r"(a[3]), "r"(b[0]), "r"(b[1]));
}

// ---------------------------------------------------------------------------
// conv_x: X fp32 -> A-fragment hi/lo fp16 planes.
// ---------------------------------------------------------------------------
__global__ void __launch_bounds__(256)
conv_x(const float* __restrict__ X) {
    const int lane = threadIdx.x & 31;
    const int wg = (blockIdx.x * 256 + threadIdx.x) >> 5;  // 0..32767
    const int r7 = lane >> 2;
    const int kb = (lane & 3) * 2;
#pragma unroll
    for (int q = 0; q < 4; q++) {
        int task = wg * 4 + q;                 // mt*16 + ks
        int mt = task >> 4, ks = task & 15;
        const float* base = X + (size_t)(mt * 16 + r7) * 256 + ks * 16 + kb;
        float2 v00 = *(const float2*)(base);
        float2 v01 = *(const float2*)(base + 8);
        float2 v10 = *(const float2*)(base + 8 * 256);
        float2 v11 = *(const float2*)(base + 8 * 256 + 8);
        uint4 hi, lo;
        hi.x = pack_hi2(v00.x, v00.y); lo.x = pack_lo2(v00.x, v00.y);
        hi.y = pack_hi2(v10.x, v10.y); lo.y = pack_lo2(v10.x, v10.y);
        hi.z = pack_hi2(v01.x, v01.y); lo.z = pack_lo2(v01.x, v01.y);
        hi.w = pack_hi2(v11.x, v11.y); lo.w = pack_lo2(v11.x, v11.y);
        size_t fi = ((size_t)task * 32 + lane) * 4;
        *(uint4*)&g_afhi[fi] = hi;
        *(uint4*)&g_aflo[fi] = lo;
    }
}

// ---------------------------------------------------------------------------
// conv_w: Wx fp32 -> single fp16 B-fragment plane.
// ---------------------------------------------------------------------------
__global__ void __launch_bounds__(256)
conv_w(const float* __restrict__ Wf, const float* __restrict__ Wi,
       const float* __restrict__ Wu, const float* __restrict__ Wo) {
    const int lane = threadIdx.x & 31;
    const int wg = (blockIdx.x * 256 + threadIdx.x) >> 5;  // 0..255
    const int n7 = lane >> 2;
    const int kb = (lane & 3) * 2;
#pragma unroll
    for (int q = 0; q < 8; q++) {
        int task = wg * 8 + q;                 // nf*16 + ks
        int nf = task >> 4, ks = task & 15;
        int n = nf * 8 + n7;
        int gate = n >> 8, j = n & 255;
        const float* Wp = (gate == 0) ? Wf : (gate == 1) ? Wi : (gate == 2) ? Wu : Wo;
        const float* base = Wp + (size_t)j * 512 + ks * 16 + kb;
        float2 v0 = *(const float2*)(base);
        float2 v1 = *(const float2*)(base + 8);
        uint2 hi;
        hi.x = pack_hi2(v0.x, v0.y);
        hi.y = pack_hi2(v1.x, v1.y);
        size_t fi = ((size_t)task * 32 + lane) * 2;
        *(uint2*)&g_wf[fi] = hi;
    }
}

// h0 -> fragment buffer parity 0 (phase-2 layout, fp16 split)
__global__ void __launch_bounds__(256)
conv_h0(const float* __restrict__ h0) {
    int idx = blockIdx.x * 256 + threadIdx.x;    // 65536
    int b = idx >> 8, j = idx & 255;
    float v = h0[idx];
    __half hh = __float2half(v);
    __half hl = __float2half(v - __half2float(hh));
    int bg = b >> 4, b_l = b & 15;
    int ks = j >> 4, kk = j & 15;
    int lp = (b_l & 7) * 4 + ((kk & 7) >> 1);
    int reg = ((b_l >> 3) & 1) | ((kk >> 3) << 1);
    int fi = (ks * 32 + lp) * 4 + reg;
    ((__half*)&g_hfhi[0][bg][fi])[kk & 1] = hh;
    ((__half*)&g_hflo[0][bg][fi])[kk & 1] = hl;
}

// ---------------------------------------------------------------------------
// Phase 1: XW = X @ Wx^T + b. (unchanged from R6)
// ---------------------------------------------------------------------------
__global__ void __launch_bounds__(256, 2)
xw_mma(const float* __restrict__ bfb, const float* __restrict__ bib,
       const float* __restrict__ bub, const float* __restrict__ bob)
{
    __shared__ uint32_t Bs[16 * 16 * 32 * 2];     // 64 KB

    const int t = threadIdx.x;
    const int lane = t & 31, wid = t >> 5;
    const int bx = blockIdx.x;
    const int wm = wid & 3;
    const int wnn = wid >> 2;
    const int mtg0 = blockIdx.y * 8 + wm * 2;
    const int nfl0 = wnn * 8;

    {
        const uint4* src = (const uint4*)(g_wf + (size_t)bx * 16384);
#pragma unroll
        for (int q = 0; q < 16; q++)
            ((uint4*)Bs)[t + q * 256] = __ldg(&src[t + q * 256]);
    }

    float c[2][8][4];
#pragma unroll
    for (int i = 0; i < 2; i++)
#pragma unroll
        for (int j = 0; j < 8; j++)
#pragma unroll
            for (int q = 0; q < 4; q++) c[i][j][q] = 0.0f;

    uint32_t ah[2][2][4], al[2][2][4];
#pragma unroll
    for (int mt2 = 0; mt2 < 2; mt2++) {
        size_t fi = (((size_t)(mtg0 + mt2) * 16) * 32 + lane) * 4;
        *(uint4*)ah[0][mt2] = __ldcg((const uint4*)&g_afhi[fi]);
        *(uint4*)al[0][mt2] = __ldcg((const uint4*)&g_aflo[fi]);
    }
    __syncthreads();

#pragma unroll 2
    for (int ks = 0; ks < 16; ks++) {
        const int cur = ks & 1, nxt = cur ^ 1;
        if (ks < 15) {
#pragma unroll
            for (int mt2 = 0; mt2 < 2; mt2++) {
                size_t fi = (((size_t)(mtg0 + mt2) * 16 + ks + 1) * 32 + lane) * 4;
                *(uint4*)ah[nxt][mt2] = __ldcg((const uint4*)&g_afhi[fi]);
                *(uint4*)al[nxt][mt2] = __ldcg((const uint4*)&g_aflo[fi]);
            }
        }
#pragma unroll
        for (int nf2 = 0; nf2 < 8; nf2++) {
            uint32_t b[2];
            *(uint2*)b = *(const uint2*)&Bs[(((nfl0 + nf2) * 16 + ks) * 32 + lane) * 2];
            mmaf16(c[0][nf2], ah[cur][0], b);
            mmaf16(c[0][nf2], al[cur][0], b);
            mmaf16(c[1][nf2], ah[cur][1], b);
            mmaf16(c[1][nf2], al[cur][1], b);
        }
    }

    const int gate = bx >> 1;
    const float* __restrict__ bias =
        (gate == 0) ? bfb : (gate == 1) ? bib : (gate == 2) ? bub : bob;
    const int jb = (bx & 1) * 128;
    const int m0 = blockIdx.y * 128;
    const int n0 = bx * 128;
#pragma unroll
    for (int mt2 = 0; mt2 < 2; mt2++) {
#pragma unroll
        for (int nf2 = 0; nf2 < 8; nf2++) {
            int row0 = wm * 32 + mt2 * 16 + (lane >> 2);
            int col0 = wnn * 64 + nf2 * 8 + (lane & 3) * 2;
            float b0 = __ldg(&bias[jb + col0]);
            float b1 = __ldg(&bias[jb + col0 + 1]);
            size_t base = (size_t)(m0 + row0) * N4 + n0 + col0;
            *(float2*)&g_xw[base] =
                make_float2(c[mt2][nf2][0] + b0, c[mt2][nf2][1] + b1);
            *(float2*)&g_xw[base + 8 * N4] =
                make_float2(c[mt2][nf2][2] + b0, c[mt2][nf2][3] + b1);
        }
    }
}

// ---------------------------------------------------------------------------
// Phase 2: persistent, 128 CTAs x 256 thr, clusters of 8 = one batch group.
// h exchanged through gmem fragment buffers (written once, read by 8 peers).
// Ordering by barrier.cluster release/acquire — NO threadfence.
// out stores after the barrier; xw[ts+1] prefetched before it.
// A-frag loads double-buffered in groups of 4 ks (bounded registers, no spill).
// ---------------------------------------------------------------------------
__global__ void __cluster_dims__(8, 1, 1) __launch_bounds__(256, 1)
qlstm_steps(const float* __restrict__ c0,
            const float* __restrict__ Wf, const float* __restrict__ Wi,
            const float* __restrict__ Wu, const float* __restrict__ Wo,
            const float* __restrict__ thf, const float* __restrict__ scf,
            const float* __restrict__ thi, const float* __restrict__ sci,
            const float* __restrict__ thu, const float* __restrict__ scu,
            const float* __restrict__ tho, const float* __restrict__ sco,
            float* __restrict__ out)
{
    extern __shared__ char smraw[];
    uint32_t* Bf = (uint32_t*)smraw;               // 16384 words (64 KB)
    float* g_s = (float*)(Bf + 16384);             // [16][132]

    const int cid = blockIdx.x;
    const int bg  = cid >> 3;
    const int jt  = cid & 7;
    const int j0  = jt * 32;

    const int t = threadIdx.x;
    const int lane = t & 31, w = t >> 5;
    const int gate = w >> 1;

    // W -> fragment-major fp16 in SMEM (one-time, single plane)
    {
        const int c = t >> 1;
        const int kb = (t & 1) * 128;
        const int gg = c >> 5;
        const float* __restrict__ Wp = (gg == 0) ? Wf : (gg == 1) ? Wi
                                       : (gg == 2) ? Wu : Wo;
        const float* src = Wp + (size_t)(j0 + (c & 31)) * 512 + 256 + kb;
        const int nf = c >> 3;
        const int lp_base = (c & 7) * 4;
#pragma unroll 8
        for (int q = 0; q < 32; q++) {
            float4 v = *(const float4*)(src + q * 4);
            float f[4] = {v.x, v.y, v.z, v.w};
#pragma unroll
            for (int e = 0; e < 4; e++) {
                int k = kb + q * 4 + e;
                int ks = k >> 4, kk = k & 15;
                int lp = lp_base + ((kk & 7) >> 1);
                int rg = kk >> 3;
                int fi = ((ks * 16 + nf) * 32 + lp) * 2 + rg;
                ((__half*)&Bf[fi])[kk & 1] = __float2half(f[e]);
            }
        }
    }

    const float* __restrict__ thp = (gate == 0) ? thf : (gate == 1) ? thi
                                    : (gate == 2) ? thu : tho;
    const float* __restrict__ scp = (gate == 0) ? scf : (gate == 1) ? sci
                                    : (gate == 2) ? scu : sco;
    float thv[2][2], scv[2][2];
#pragma unroll
    for (int i2 = 0; i2 < 2; i2++) {
        int cc = (2 * w + i2) * 8 + (lane & 3) * 2;
        thv[i2][0] = thp[j0 + (cc & 31)];
        thv[i2][1] = thp[j0 + ((cc + 1) & 31)];
        scv[i2][0] = scp[j0 + (cc & 31)];
        scv[i2][1] = scp[j0 + ((cc + 1) & 31)];
    }
    const float va = (gate == 2) ? 2.0f : 1.0f;
    const float vb = (gate == 2) ? 2.0f : 1.0f;
    const float vc = (gate == 2) ? -1.0f : 0.0f;

    float c_reg[2];
#pragma unroll
    for (int p = 0; p < 2; p++) {
        int s = t + p * 256;
        c_reg[p] = c0[(size_t)(bg * 16 + (s >> 5)) * 256 + j0 + (s & 31)];
    }

    // initial xw prefetch for ts = 0
    float2 xwv[2][2];
#pragma unroll
    for (int rr = 0; rr < 2; rr++) {
        int b = bg * 16 + (lane >> 2) + rr * 8;
#pragma unroll
        for (int i2 = 0; i2 < 2; i2++) {
            int cc = (2 * w + i2) * 8 + (lane & 3) * 2;
            int n = gate * 256 + j0 + (cc & 31);
            xwv[rr][i2] = __ldcg((const float2*)&g_xw[((size_t)b) * N4 + n]);
        }
    }

    __syncthreads();

    for (int ts = 0; ts < SEQ; ts++) {
        const int rp = ts & 1, wp2 = (ts + 1) & 1;
        const bool last = (ts == SEQ - 1);

        // ---- GEMM 16 x 128 x 256: A frags from gmem (L2), split acc chains
        float acch[2][4], accl[2][4];
#pragma unroll
        for (int i2 = 0; i2 < 2; i2++)
#pragma unroll
            for (int q = 0; q < 4; q++) { acch[i2][q] = 0.0f; accl[i2][q] = 0.0f; }

        const uint32_t* __restrict__ fhi = g_hfhi[rp][bg];
        const uint32_t* __restrict__ flo = g_hflo[rp][bg];

        // double-buffered groups of 4 ks (16 LDG.128 in flight max)
        uint32_t ahb[2][4][4], alb[2][4][4];
#pragma unroll
        for (int k4 = 0; k4 < 4; k4++) {
            *(uint4*)ahb[0][k4] = __ldcg((const uint4*)&fhi[(k4 * 32 + lane) * 4]);
            *(uint4*)alb[0][k4] = __ldcg((const uint4*)&flo[(k4 * 32 + lane) * 4]);
        }
#pragma unroll
        for (int g = 0; g < 4; g++) {
            const int cur = g & 1, nxt = cur ^ 1;
            if (g < 3) {
#pragma unroll
                for (int k4 = 0; k4 < 4; k4++) {
                    int ks = (g + 1) * 4 + k4;
                    *(uint4*)ahb[nxt][k4] = __ldcg((const uint4*)&fhi[(ks * 32 + lane) * 4]);
                    *(uint4*)alb[nxt][k4] = __ldcg((const uint4*)&flo[(ks * 32 + lane) * 4]);
                }
            }
#pragma unroll
            for (int k4 = 0; k4 < 4; k4++) {
                int ks = g * 4 + k4;
#pragma unroll
                for (int i2 = 0; i2 < 2; i2++) {
                    int nf = 2 * w + i2;
                    uint32_t b[2];
                    *(uint2*)b = *(const uint2*)&Bf[((ks * 16 + nf) * 32 + lane) * 2];
                    mmaf16(acch[i2], ahb[cur][k4], b);
                    mmaf16(accl[i2], alb[cur][k4], b);
                }
            }
        }

        // ---- nonlinearities -> g_s ----
#pragma unroll
        for (int i2 = 0; i2 < 2; i2++) {
            int cc = (2 * w + i2) * 8 + (lane & 3) * 2;
#pragma unroll
            for (int rr = 0; rr < 2; rr++) {
                int row = (lane >> 2) + rr * 8;
                float z0 = acch[i2][rr * 2]     + accl[i2][rr * 2]     + xwv[rr][i2].x;
                float z1 = acch[i2][rr * 2 + 1] + accl[i2][rr * 2 + 1] + xwv[rr][i2].y;
                float q0 = sigmoidf_(__sinf(z0 * thv[i2][0]) * scv[i2][0]);
                float q1 = sigmoidf_(__sinf(z1 * thv[i2][1]) * scv[i2][1]);
                g_s[row * 132 + cc]     = va * sigmoidf_(vb * q0) + vc;
                g_s[row * 132 + cc + 1] = va * sigmoidf_(vb * q1) + vc;
            }
        }
        __syncthreads();

        // ---- state update + h frag stores (skip stores on last step) ----
        float h_out[2], c_out[2];
#pragma unroll
        for (int p = 0; p < 2; p++) {
            int s = t + p * 256;
            int b_l = s >> 5, jj = s & 31;
            float fv = g_s[b_l * 132 +       jj];
            float iv = g_s[b_l * 132 +  32 + jj];
            float uv = g_s[b_l * 132 +  64 + jj];
            float ov = g_s[b_l * 132 +  96 + jj];
            float cc = fv * c_reg[p] + iv * uv;
            c_reg[p] = cc;
            c_out[p] = cc;
            float h = ov * tanhf_fast(cc);
            h_out[p] = h;

            // pack pair; even lane stores hi word, odd lane stores lo word
            __half hh = __float2half(h);
            __half hl = __float2half(h - __half2float(hh));
            uint32_t mine = packh2(hh, hl);
            uint32_t peer = __shfl_xor_sync(0xffffffffu, mine, 1);
            if (!last) {
                int j = j0 + jj;
                int ks = j >> 4, kk = j & 15;
                int lp = (b_l & 7) * 4 + ((kk & 7) >> 1);
                int rg = ((b_l >> 3) & 1) | ((kk >> 3) << 1);
                int fi = (ks * 32 + lp) * 4 + rg;
                if (!(t & 1)) {
                    g_hfhi[wp2][bg][fi] = (mine & 0xffffu) | (peer << 16);
                } else {
                    g_hflo[wp2][bg][fi] = (peer >> 16) | (mine & 0xffff0000u);
                }
            }
        }

        if (!last) {
            // prefetch xw for ts+1 (recurrence-independent; hides under barrier)
#pragma unroll
            for (int rr = 0; rr < 2; rr++) {
                int b = bg * 16 + (lane >> 2) + rr * 8;
#pragma unroll
                for (int i2 = 0; i2 < 2; i2++) {
                    int cc = (2 * w + i2) * 8 + (lane & 3) * 2;
                    int n = gate * 256 + j0 + (cc & 31);
                    xwv[rr][i2] = __ldcg((const float2*)
                        &g_xw[((size_t)(ts + 1) * BATCH + b) * N4 + n]);
                }
            }
            // release/acquire ordering for the gmem frag exchange
            asm volatile("barrier.cluster.arrive.aligned;" ::: "memory");
            asm volatile("barrier.cluster.wait.aligned;" ::: "memory");
        }

        // ---- out stores (after barrier: off the recurrence critical path) ----
#pragma unroll
        for (int p = 0; p < 2; p++) {
            int s = t + p * 256;
            int b = bg * 16 + (s >> 5);
            int j = j0 + (s & 31);
            out[((size_t)ts * BATCH + b) * HID + j] = h_out[p];
            if (last) {
                size_t sidx = (size_t)b * HID + j;
                out[OUT_SEQ_ELEMS + sidx] = h_out[p];
                out[OUT_SEQ_ELEMS + (size_t)BATCH * HID + sidx] = c_out[p];
            }
        }
    }
}

// ---------------------------------------------------------------------------
extern "C" void kernel_launch(void* const* d_in, const int* in_sizes, int n_in,
                              void* d_out, int out_size)
{
    (void)in_sizes; (void)n_in; (void)out_size;
    const float* inputs = (const float*)d_in[0];
    const float* h0  = (const float*)d_in[1];
    const float* c0  = (const float*)d_in[2];
    const float* Wf  = (const float*)d_in[3];
    const float* bf  = (const float*)d_in[4];
    const float* thf = (const float*)d_in[5];
    const float* scf = (const float*)d_in[6];
    const float* Wi  = (const float*)d_in[7];
    const float* bi  = (const float*)d_in[8];
    const float* thi = (const float*)d_in[9];
    const float* sci = (const float*)d_in[10];
    const float* Wu  = (const float*)d_in[11];
    const float* bu  = (const float*)d_in[12];
    const float* thu = (const float*)d_in[13];
    const float* scu = (const float*)d_in[14];
    const float* Wo  = (const float*)d_in[15];
    const float* bo  = (const float*)d_in[16];
    const float* tho = (const float*)d_in[17];
    const float* sco = (const float*)d_in[18];
    float* out = (float*)d_out;

    conv_x<<<4096, 256>>>(inputs);
    conv_w<<<32, 256>>>(Wf, Wi, Wu, Wo);
    conv_h0<<<256, 256>>>(h0);

    dim3 g1(8, GM_M / 128);
    xw_mma<<<g1, 256>>>(bf, bi, bu, bo);

    const int smem2 = 16384 * 4 + 16 * 132 * 4;   // 65536 + 8448
    cudaFuncSetAttribute(qlstm_steps, cudaFuncAttributeMaxDynamicSharedMemorySize, smem2);
    qlstm_steps<<<128, 256, smem2>>>(c0, Wf, Wi, Wu, Wo,
                                     thf, scf, thi, sci, thu, scu, tho, sco,
                                     out);
}

// round 13
// speedup vs baseline: 1.4840x; 1.4840x over previous
#include <cuda_runtime.h>
#include <cuda_fp16.h>
#include <cstdint>

#define SEQ 512
#define BATCH 256
#define HID 256
#define N4 1024
#define GM_M (SEQ * BATCH)                           // 131072 rows
#define OUT_SEQ_ELEMS ((size_t)SEQ * BATCH * HID)    // 33554432

// scratch
__device__ float g_xw[(size_t)SEQ * BATCH * N4];                 // 512 MB

// A fragments of X (hi/lo fp16 planes): [mt 8192][ks 16][lane 32][reg 4] uint32
__device__ uint32_t g_afhi[(size_t)8192 * 16 * 32 * 4];          // 64 MB
__device__ uint32_t g_aflo[(size_t)8192 * 16 * 32 * 4];          // 64 MB
// B fragments of Wx (single fp16 plane): [nf 128][ks 16][lane 32][reg 2]
__device__ uint32_t g_wf[128 * 16 * 32 * 2];                     // 512 KB

// h fragment buffers: [parity][bg][ (ks*32 + lane)*4 + reg ] uint32 (2 fp16)
#define FRAG_WORDS (16 * 32 * 4)
__device__ uint32_t g_hfhi[2][16][FRAG_WORDS];
__device__ uint32_t g_hflo[2][16][FRAG_WORDS];

// ---------------------------------------------------------------------------
// helpers
// ---------------------------------------------------------------------------
__device__ __forceinline__ float sigmoidf_(float x) {
    return __fdividef(1.0f, 1.0f + __expf(-x));
}
__device__ __forceinline__ float tanhf_fast(float x) {
    return 2.0f * sigmoidf_(2.0f * x) - 1.0f;
}
__device__ __forceinline__ uint32_t packh2(__half a, __half b) {
    return (uint32_t)__half_as_ushort(a) | ((uint32_t)__half_as_ushort(b) << 16);
}
__device__ __forceinline__ uint32_t pack_hi2(float a, float b) {
    return packh2(__float2half(a), __float2half(b));
}
__device__ __forceinline__ uint32_t pack_lo2(float a, float b) {
    __half ha = __float2half(a), hb = __float2half(b);
    return packh2(__float2half(a - __half2float(ha)),
                  __float2half(b - __half2float(hb)));
}

// legacy tensor-core mma fp16 (compute_80 PTX — compiles under compute_103)
__device__ __forceinline__ void mmaf16(float* c, const uint32_t* a, const uint32_t* b) {
    asm volatile(
        "mma.sync.aligned.m16n8k16.row.col.f32.f16.f16.f32 "
        "{%0,%1,%2,%3}, {%4,%5,%6,%7}, {%8,%9}, {%0,%1,%2,%3};"
        : "+f"(c[0]), "+f"(c[1]), "+f"(c[2]), "+f"(c[3])
        : "r"(a[0]), "r"(a[1]), "r"(a[2]), "r"(a[3]), "r"(b[0]), "r"(b[1]));
}

// ---------------------------------------------------------------------------
// conv_all: one launch, block-range dispatch.
//   blocks [0, 4096)        : X fp32 -> A-fragment hi/lo fp16 planes
//   blocks [4096, 4128)     : Wx fp32 -> fp16 B-fragment plane
//   blocks [4128, 4384)     : h0 -> fragment buffer parity 0
// ---------------------------------------------------------------------------
__global__ void __launch_bounds__(256)
conv_all(const float* __restrict__ X,
         const float* __restrict__ Wf, const float* __restrict__ Wi,
         const float* __restrict__ Wu, const float* __restrict__ Wo,
         const float* __restrict__ h0) {
    const int bid = blockIdx.x;
    const int lane = threadIdx.x & 31;

    if (bid < 4096) {
        // ---- conv_x ----
        const int wg = (bid * 256 + threadIdx.x) >> 5;  // 0..32767
        const int r7 = lane >> 2;
        const int kb = (lane & 3) * 2;
#pragma unroll
        for (int q = 0; q < 4; q++) {
            int task = wg * 4 + q;                 // mt*16 + ks
            int mt = task >> 4, ks = task & 15;
            const float* base = X + (size_t)(mt * 16 + r7) * 256 + ks * 16 + kb;
            float2 v00 = *(const float2*)(base);
            float2 v01 = *(const float2*)(base + 8);
            float2 v10 = *(const float2*)(base + 8 * 256);
            float2 v11 = *(const float2*)(base + 8 * 256 + 8);
            uint4 hi, lo;
            hi.x = pack_hi2(v00.x, v00.y); lo.x = pack_lo2(v00.x, v00.y);
            hi.y = pack_hi2(v10.x, v10.y); lo.y = pack_lo2(v10.x, v10.y);
            hi.z = pack_hi2(v01.x, v01.y); lo.z = pack_lo2(v01.x, v01.y);
            hi.w = pack_hi2(v11.x, v11.y); lo.w = pack_lo2(v11.x, v11.y);
            size_t fi = ((size_t)task * 32 + lane) * 4;
            *(uint4*)&g_afhi[fi] = hi;
            *(uint4*)&g_aflo[fi] = lo;
        }
    } else if (bid < 4128) {
        // ---- conv_w ----
        const int wg = ((bid - 4096) * 256 + threadIdx.x) >> 5;  // 0..255
        const int n7 = lane >> 2;
        const int kb = (lane & 3) * 2;
#pragma unroll
        for (int q = 0; q < 8; q++) {
            int task = wg * 8 + q;                 // nf*16 + ks
            int nf = task >> 4, ks = task & 15;
            int n = nf * 8 + n7;
            int gate = n >> 8, j = n & 255;
            const float* Wp = (gate == 0) ? Wf : (gate == 1) ? Wi : (gate == 2) ? Wu : Wo;
            const float* base = Wp + (size_t)j * 512 + ks * 16 + kb;
            float2 v0 = *(const float2*)(base);
            float2 v1 = *(const float2*)(base + 8);
            uint2 hi;
            hi.x = pack_hi2(v0.x, v0.y);
            hi.y = pack_hi2(v1.x, v1.y);
            size_t fi = ((size_t)task * 32 + lane) * 2;
            *(uint2*)&g_wf[fi] = hi;
        }
    } else {
        // ---- conv_h0 ----
        int idx = (bid - 4128) * 256 + threadIdx.x;    // 65536
        int b = idx >> 8, j = idx & 255;
        float v = h0[idx];
        __half hh = __float2half(v);
        __half hl = __float2half(v - __half2float(hh));
        int bg = b >> 4, b_l = b & 15;
        int ks = j >> 4, kk = j & 15;
        int lp = (b_l & 7) * 4 + ((kk & 7) >> 1);
        int reg = ((b_l >> 3) & 1) | ((kk >> 3) << 1);
        int fi = (ks * 32 + lp) * 4 + reg;
        ((__half*)&g_hfhi[0][bg][fi])[kk & 1] = hh;
        ((__half*)&g_hflo[0][bg][fi])[kk & 1] = hl;
    }
}

// ---------------------------------------------------------------------------
// Phase 1: XW = X @ Wx^T + b. (unchanged from R6)
// ---------------------------------------------------------------------------
__global__ void __launch_bounds__(256, 2)
xw_mma(const float* __restrict__ bfb, const float* __restrict__ bib,
       const float* __restrict__ bub, const float* __restrict__ bob)
{
    __shared__ uint32_t Bs[16 * 16 * 32 * 2];     // 64 KB

    const int t = threadIdx.x;
    const int lane = t & 31, wid = t >> 5;
    const int bx = blockIdx.x;
    const int wm = wid & 3;
    const int wnn = wid >> 2;
    const int mtg0 = blockIdx.y * 8 + wm * 2;
    const int nfl0 = wnn * 8;

    {
        const uint4* src = (const uint4*)(g_wf + (size_t)bx * 16384);
#pragma unroll
        for (int q = 0; q < 16; q++)
            ((uint4*)Bs)[t + q * 256] = __ldg(&src[t + q * 256]);
    }

    float c[2][8][4];
#pragma unroll
    for (int i = 0; i < 2; i++)
#pragma unroll
        for (int j = 0; j < 8; j++)
#pragma unroll
            for (int q = 0; q < 4; q++) c[i][j][q] = 0.0f;

    uint32_t ah[2][2][4], al[2][2][4];
#pragma unroll
    for (int mt2 = 0; mt2 < 2; mt2++) {
        size_t fi = (((size_t)(mtg0 + mt2) * 16) * 32 + lane) * 4;
        *(uint4*)ah[0][mt2] = __ldcg((const uint4*)&g_afhi[fi]);
        *(uint4*)al[0][mt2] = __ldcg((const uint4*)&g_aflo[fi]);
    }
    __syncthreads();

#pragma unroll 2
    for (int ks = 0; ks < 16; ks++) {
        const int cur = ks & 1, nxt = cur ^ 1;
        if (ks < 15) {
#pragma unroll
            for (int mt2 = 0; mt2 < 2; mt2++) {
                size_t fi = (((size_t)(mtg0 + mt2) * 16 + ks + 1) * 32 + lane) * 4;
                *(uint4*)ah[nxt][mt2] = __ldcg((const uint4*)&g_afhi[fi]);
                *(uint4*)al[nxt][mt2] = __ldcg((const uint4*)&g_aflo[fi]);
            }
        }
#pragma unroll
        for (int nf2 = 0; nf2 < 8; nf2++) {
            uint32_t b[2];
            *(uint2*)b = *(const uint2*)&Bs[(((nfl0 + nf2) * 16 + ks) * 32 + lane) * 2];
            mmaf16(c[0][nf2], ah[cur][0], b);
            mmaf16(c[0][nf2], al[cur][0], b);
            mmaf16(c[1][nf2], ah[cur][1], b);
            mmaf16(c[1][nf2], al[cur][1], b);
        }
    }

    const int gate = bx >> 1;
    const float* __restrict__ bias =
        (gate == 0) ? bfb : (gate == 1) ? bib : (gate == 2) ? bub : bob;
    const int jb = (bx & 1) * 128;
    const int m0 = blockIdx.y * 128;
    const int n0 = bx * 128;
#pragma unroll
    for (int mt2 = 0; mt2 < 2; mt2++) {
#pragma unroll
        for (int nf2 = 0; nf2 < 8; nf2++) {
            int row0 = wm * 32 + mt2 * 16 + (lane >> 2);
            int col0 = wnn * 64 + nf2 * 8 + (lane & 3) * 2;
            float b0 = __ldg(&bias[jb + col0]);
            float b1 = __ldg(&bias[jb + col0 + 1]);
            size_t base = (size_t)(m0 + row0) * N4 + n0 + col0;
            *(float2*)&g_xw[base] =
                make_float2(c[mt2][nf2][0] + b0, c[mt2][nf2][1] + b1);
            *(float2*)&g_xw[base + 8 * N4] =
                make_float2(c[mt2][nf2][2] + b0, c[mt2][nf2][3] + b1);
        }
    }
}

// ---------------------------------------------------------------------------
// Phase 2: persistent, 128 CTAs x 256 thr, clusters of 8 = one batch group.
// EXACT R9 structure (2340 us): gmem frag exchange, barrier.cluster ordering,
// unroll-4 ks loop, xw[ts+1] prefetch before barrier, out stores after it.
// ---------------------------------------------------------------------------
__global__ void __cluster_dims__(8, 1, 1) __launch_bounds__(256, 1)
qlstm_steps(const float* __restrict__ c0,
            const float* __restrict__ Wf, const float* __restrict__ Wi,
            const float* __restrict__ Wu, const float* __restrict__ Wo,
            const float* __restrict__ thf, const float* __restrict__ scf,
            const float* __restrict__ thi, const float* __restrict__ sci,
            const float* __restrict__ thu, const float* __restrict__ scu,
            const float* __restrict__ tho, const float* __restrict__ sco,
            float* __restrict__ out)
{
    extern __shared__ char smraw[];
    uint32_t* Bf = (uint32_t*)smraw;               // 16384 words (64 KB)
    float* g_s = (float*)(Bf + 16384);             // [16][132]

    const int cid = blockIdx.x;
    const int bg  = cid >> 3;
    const int jt  = cid & 7;
    const int j0  = jt * 32;

    const int t = threadIdx.x;
    const int lane = t & 31, w = t >> 5;
    const int gate = w >> 1;

    // W -> fragment-major fp16 in SMEM (one-time, single plane)
    {
        const int c = t >> 1;
        const int kb = (t & 1) * 128;
        const int gg = c >> 5;
        const float* __restrict__ Wp = (gg == 0) ? Wf : (gg == 1) ? Wi
                                       : (gg == 2) ? Wu : Wo;
        const float* src = Wp + (size_t)(j0 + (c & 31)) * 512 + 256 + kb;
        const int nf = c >> 3;
        const int lp_base = (c & 7) * 4;
#pragma unroll 8
        for (int q = 0; q < 32; q++) {
            float4 v = *(const float4*)(src + q * 4);
            float f[4] = {v.x, v.y, v.z, v.w};
#pragma unroll
            for (int e = 0; e < 4; e++) {
                int k = kb + q * 4 + e;
                int ks = k >> 4, kk = k & 15;
                int lp = lp_base + ((kk & 7) >> 1);
                int rg = kk >> 3;
                int fi = ((ks * 16 + nf) * 32 + lp) * 2 + rg;
                ((__half*)&Bf[fi])[kk & 1] = __float2half(f[e]);
            }
        }
    }

    const float* __restrict__ thp = (gate == 0) ? thf : (gate == 1) ? thi
                                    : (gate == 2) ? thu : tho;
    const float* __restrict__ scp = (gate == 0) ? scf : (gate == 1) ? sci
                                    : (gate == 2) ? scu : sco;
    float thv[2][2], scv[2][2];
#pragma unroll
    for (int i2 = 0; i2 < 2; i2++) {
        int cc = (2 * w + i2) * 8 + (lane & 3) * 2;
        thv[i2][0] = thp[j0 + (cc & 31)];
        thv[i2][1] = thp[j0 + ((cc + 1) & 31)];
        scv[i2][0] = scp[j0 + (cc & 31)];
        scv[i2][1] = scp[j0 + ((cc + 1) & 31)];
    }
    const float va = (gate == 2) ? 2.0f : 1.0f;
    const float vb = (gate == 2) ? 2.0f : 1.0f;
    const float vc = (gate == 2) ? -1.0f : 0.0f;

    float c_reg[2];
#pragma unroll
    for (int p = 0; p < 2; p++) {
        int s = t + p * 256;
        c_reg[p] = c0[(size_t)(bg * 16 + (s >> 5)) * 256 + j0 + (s & 31)];
    }

    // initial xw prefetch for ts = 0
    float2 xwv[2][2];
#pragma unroll
    for (int rr = 0; rr < 2; rr++) {
        int b = bg * 16 + (lane >> 2) + rr * 8;
#pragma unroll
        for (int i2 = 0; i2 < 2; i2++) {
            int cc = (2 * w + i2) * 8 + (lane & 3) * 2;
            int n = gate * 256 + j0 + (cc & 31);
            xwv[rr][i2] = __ldcg((const float2*)&g_xw[((size_t)b) * N4 + n]);
        }
    }

    __syncthreads();

    for (int ts = 0; ts < SEQ; ts++) {
        const int rp = ts & 1, wp2 = (ts + 1) & 1;
        const bool last = (ts == SEQ - 1);

        // ---- GEMM 16 x 128 x 256: A frags from gmem (L2), split acc chains
        float acch[2][4], accl[2][4];
#pragma unroll
        for (int i2 = 0; i2 < 2; i2++)
#pragma unroll
            for (int q = 0; q < 4; q++) { acch[i2][q] = 0.0f; accl[i2][q] = 0.0f; }

        const uint32_t* __restrict__ fhi = g_hfhi[rp][bg];
        const uint32_t* __restrict__ flo = g_hflo[rp][bg];
#pragma unroll 4
        for (int ks = 0; ks < 16; ks++) {
            uint32_t ah[4], al[4];
            *(uint4*)ah = __ldcg((const uint4*)&fhi[(ks * 32 + lane) * 4]);
            *(uint4*)al = __ldcg((const uint4*)&flo[(ks * 32 + lane) * 4]);
#pragma unroll
            for (int i2 = 0; i2 < 2; i2++) {
                int nf = 2 * w + i2;
                uint32_t b[2];
                *(uint2*)b = *(const uint2*)&Bf[((ks * 16 + nf) * 32 + lane) * 2];
                mmaf16(acch[i2], ah, b);
                mmaf16(accl[i2], al, b);
            }
        }

        // ---- nonlinearities -> g_s ----
#pragma unroll
        for (int i2 = 0; i2 < 2; i2++) {
            int cc = (2 * w + i2) * 8 + (lane & 3) * 2;
#pragma unroll
            for (int rr = 0; rr < 2; rr++) {
                int row = (lane >> 2) + rr * 8;
                float z0 = acch[i2][rr * 2]     + accl[i2][rr * 2]     + xwv[rr][i2].x;
                float z1 = acch[i2][rr * 2 + 1] + accl[i2][rr * 2 + 1] + xwv[rr][i2].y;
                float q0 = sigmoidf_(__sinf(z0 * thv[i2][0]) * scv[i2][0]);
                float q1 = sigmoidf_(__sinf(z1 * thv[i2][1]) * scv[i2][1]);
                g_s[row * 132 + cc]     = va * sigmoidf_(vb * q0) + vc;
                g_s[row * 132 + cc + 1] = va * sigmoidf_(vb * q1) + vc;
            }
        }
        __syncthreads();

        // ---- state update + h frag stores (skip stores on last step) ----
        float h_out[2], c_out[2];
#pragma unroll
        for (int p = 0; p < 2; p++) {
            int s = t + p * 256;
            int b_l = s >> 5, jj = s & 31;
            float fv = g_s[b_l * 132 +       jj];
            float iv = g_s[b_l * 132 +  32 + jj];
            float uv = g_s[b_l * 132 +  64 + jj];
            float ov = g_s[b_l * 132 +  96 + jj];
            float cc = fv * c_reg[p] + iv * uv;
            c_reg[p] = cc;
            c_out[p] = cc;
            float h = ov * tanhf_fast(cc);
            h_out[p] = h;

            // pack pair; even lane stores hi word, odd lane stores lo word
            __half hh = __float2half(h);
            __half hl = __float2half(h - __half2float(hh));
            uint32_t mine = packh2(hh, hl);
            uint32_t peer = __shfl_xor_sync(0xffffffffu, mine, 1);
            if (!last) {
                int j = j0 + jj;
                int ks = j >> 4, kk = j & 15;
                int lp = (b_l & 7) * 4 + ((kk & 7) >> 1);
                int rg = ((b_l >> 3) & 1) | ((kk >> 3) << 1);
                int fi = (ks * 32 + lp) * 4 + rg;
                if (!(t & 1)) {
                    g_hfhi[wp2][bg][fi] = (mine & 0xffffu) | (peer << 16);
                } else {
                    g_hflo[wp2][bg][fi] = (peer >> 16) | (mine & 0xffff0000u);
                }
            }
        }

        if (!last) {
            // prefetch xw for ts+1 (recurrence-independent; hides under barrier)
#pragma unroll
            for (int rr = 0; rr < 2; rr++) {
                int b = bg * 16 + (lane >> 2) + rr * 8;
#pragma unroll
                for (int i2 = 0; i2 < 2; i2++) {
                    int cc = (2 * w + i2) * 8 + (lane & 3) * 2;
                    int n = gate * 256 + j0 + (cc & 31);
                    xwv[rr][i2] = __ldcg((const float2*)
                        &g_xw[((size_t)(ts + 1) * BATCH + b) * N4 + n]);
                }
            }
            // release/acquire ordering for the gmem frag exchange
            asm volatile("barrier.cluster.arrive.aligned;" ::: "memory");
            asm volatile("barrier.cluster.wait.aligned;" ::: "memory");
        }

        // ---- out stores (after barrier: off the recurrence critical path) ----
#pragma unroll
        for (int p = 0; p < 2; p++) {
            int s = t + p * 256;
            int b = bg * 16 + (s >> 5);
            int j = j0 + (s & 31);
            out[((size_t)ts * BATCH + b) * HID + j] = h_out[p];
            if (last) {
                size_t sidx = (size_t)b * HID + j;
                out[OUT_SEQ_ELEMS + sidx] = h_out[p];
                out[OUT_SEQ_ELEMS + (size_t)BATCH * HID + sidx] = c_out[p];
            }
        }
    }
}

// ---------------------------------------------------------------------------
extern "C" void kernel_launch(void* const* d_in, const int* in_sizes, int n_in,
                              void* d_out, int out_size)
{
    (void)in_sizes; (void)n_in; (void)out_size;
    const float* inputs = (const float*)d_in[0];
    const float* h0  = (const float*)d_in[1];
    const float* c0  = (const float*)d_in[2];
    const float* Wf  = (const float*)d_in[3];
    const float* bf  = (const float*)d_in[4];
    const float* thf = (const float*)d_in[5];
    const float* scf = (const float*)d_in[6];
    const float* Wi  = (const float*)d_in[7];
    const float* bi  = (const float*)d_in[8];
    const float* thi = (const float*)d_in[9];
    const float* sci = (const float*)d_in[10];
    const float* Wu  = (const float*)d_in[11];
    const float* bu  = (const float*)d_in[12];
    const float* thu = (const float*)d_in[13];
    const float* scu = (const float*)d_in[14];
    const float* Wo  = (const float*)d_in[15];
    const float* bo  = (const float*)d_in[16];
    const float* tho = (const float*)d_in[17];
    const float* sco = (const float*)d_in[18];
    float* out = (float*)d_out;

    // fused conversions (X A-frags + W B-frags + h0 frags) in one launch
    conv_all<<<4384, 256>>>(inputs, Wf, Wi, Wu, Wo, h0);

    dim3 g1(8, GM_M / 128);
    xw_mma<<<g1, 256>>>(bf, bi, bu, bo);

    const int smem2 = 16384 * 4 + 16 * 132 * 4;   // 65536 + 8448
    cudaFuncSetAttribute(qlstm_steps, cudaFuncAttributeMaxDynamicSharedMemorySize, smem2);
    qlstm_steps<<<128, 256, smem2>>>(c0, Wf, Wi, Wu, Wo,
                                     thf, scf, thi, sci, thu, scu, tho, sco,
                                     out);
}

// round 14
// speedup vs baseline: 1.8975x; 1.2787x over previous
#include <cuda_runtime.h>
#include <cuda_fp16.h>
#include <cstdint>

#define SEQ 512
#define BATCH 256
#define HID 256
#define N4 1024
#define GM_M (SEQ * BATCH)                           // 131072 rows
#define OUT_SEQ_ELEMS ((size_t)SEQ * BATCH * HID)    // 33554432

// scratch
__device__ float g_xw[(size_t)SEQ * BATCH * N4];                 // 512 MB

// A fragments of X (single fp16 plane): [mt 8192][ks 16][lane 32][reg 4] uint32
__device__ uint32_t g_af[(size_t)8192 * 16 * 32 * 4];            // 64 MB
// B fragments of Wx (single fp16 plane): [nf 128][ks 16][lane 32][reg 2]
__device__ uint32_t g_wf[128 * 16 * 32 * 2];                     // 512 KB

// h fragment buffers (single fp16 plane): [parity][bg][frag words]
#define FRAG_WORDS (16 * 32 * 4)
__device__ uint32_t g_hf[2][16][FRAG_WORDS];

// ---------------------------------------------------------------------------
// helpers
// ---------------------------------------------------------------------------
__device__ __forceinline__ float sigmoidf_(float x) {
    return __fdividef(1.0f, 1.0f + __expf(-x));
}
__device__ __forceinline__ float tanhf_fast(float x) {
    return 2.0f * sigmoidf_(2.0f * x) - 1.0f;
}
__device__ __forceinline__ uint32_t packh2(__half a, __half b) {
    return (uint32_t)__half_as_ushort(a) | ((uint32_t)__half_as_ushort(b) << 16);
}
__device__ __forceinline__ uint32_t pack_hi2(float a, float b) {
    return packh2(__float2half(a), __float2half(b));
}

// legacy tensor-core mma fp16 (compute_80 PTX — compiles under compute_103)
__device__ __forceinline__ void mmaf16(float* c, const uint32_t* a, const uint32_t* b) {
    asm volatile(
        "mma.sync.aligned.m16n8k16.row.col.f32.f16.f16.f32 "
        "{%0,%1,%2,%3}, {%4,%5,%6,%7}, {%8,%9}, {%0,%1,%2,%3};"
        : "+f"(c[0]), "+f"(c[1]), "+f"(c[2]), "+f"(c[3])
        : "r"(a[0]), "r"(a[1]), "r"(a[2]), "r"(a[3]), "r"(b[0]), "r"(b[1]));
}

// ---------------------------------------------------------------------------
// conv_all: one launch, block-range dispatch.
//   blocks [0, 4096)        : X fp32 -> A-fragment fp16 plane
//   blocks [4096, 4128)     : Wx fp32 -> fp16 B-fragment plane
//   blocks [4128, 4384)     : h0 -> fragment buffer parity 0
// ---------------------------------------------------------------------------
__global__ void __launch_bounds__(256)
conv_all(const float* __restrict__ X,
         const float* __restrict__ Wf, const float* __restrict__ Wi,
         const float* __restrict__ Wu, const float* __restrict__ Wo,
         const float* __restrict__ h0) {
    const int bid = blockIdx.x;
    const int lane = threadIdx.x & 31;

    if (bid < 4096) {
        // ---- conv_x ----
        const int wg = (bid * 256 + threadIdx.x) >> 5;  // 0..32767
        const int r7 = lane >> 2;
        const int kb = (lane & 3) * 2;
#pragma unroll
        for (int q = 0; q < 4; q++) {
            int task = wg * 4 + q;                 // mt*16 + ks
            int mt = task >> 4, ks = task & 15;
            const float* base = X + (size_t)(mt * 16 + r7) * 256 + ks * 16 + kb;
            float2 v00 = *(const float2*)(base);
            float2 v01 = *(const float2*)(base + 8);
            float2 v10 = *(const float2*)(base + 8 * 256);
            float2 v11 = *(const float2*)(base + 8 * 256 + 8);
            uint4 hi;
            hi.x = pack_hi2(v00.x, v00.y);
            hi.y = pack_hi2(v10.x, v10.y);
            hi.z = pack_hi2(v01.x, v01.y);
            hi.w = pack_hi2(v11.x, v11.y);
            size_t fi = ((size_t)task * 32 + lane) * 4;
            *(uint4*)&g_af[fi] = hi;
        }
    } else if (bid < 4128) {
        // ---- conv_w ----
        const int wg = ((bid - 4096) * 256 + threadIdx.x) >> 5;  // 0..255
        const int n7 = lane >> 2;
        const int kb = (lane & 3) * 2;
#pragma unroll
        for (int q = 0; q < 8; q++) {
            int task = wg * 8 + q;                 // nf*16 + ks
            int nf = task >> 4, ks = task & 15;
            int n = nf * 8 + n7;
            int gate = n >> 8, j = n & 255;
            const float* Wp = (gate == 0) ? Wf : (gate == 1) ? Wi : (gate == 2) ? Wu : Wo;
            const float* base = Wp + (size_t)j * 512 + ks * 16 + kb;
            float2 v0 = *(const float2*)(base);
            float2 v1 = *(const float2*)(base + 8);
            uint2 hi;
            hi.x = pack_hi2(v0.x, v0.y);
            hi.y = pack_hi2(v1.x, v1.y);
            size_t fi = ((size_t)task * 32 + lane) * 2;
            *(uint2*)&g_wf[fi] = hi;
        }
    } else {
        // ---- conv_h0 ----
        int idx = (bid - 4128) * 256 + threadIdx.x;    // 65536
        int b = idx >> 8, j = idx & 255;
        float v = h0[idx];
        __half hh = __float2half(v);
        int bg = b >> 4, b_l = b & 15;
        int ks = j >> 4, kk = j & 15;
        int lp = (b_l & 7) * 4 + ((kk & 7) >> 1);
        int reg = ((b_l >> 3) & 1) | ((kk >> 3) << 1);
        int fi = (ks * 32 + lp) * 4 + reg;
        ((__half*)&g_hf[0][bg][fi])[kk & 1] = hh;
    }
}

// ---------------------------------------------------------------------------
// Phase 1: XW = X @ Wx^T + b. Single fp16 plane (pure fp16 MMA, fp32 accum).
// ---------------------------------------------------------------------------
__global__ void __launch_bounds__(256, 2)
xw_mma(const float* __restrict__ bfb, const float* __restrict__ bib,
       const float* __restrict__ bub, const float* __restrict__ bob)
{
    __shared__ uint32_t Bs[16 * 16 * 32 * 2];     // 64 KB

    const int t = threadIdx.x;
    const int lane = t & 31, wid = t >> 5;
    const int bx = blockIdx.x;
    const int wm = wid & 3;
    const int wnn = wid >> 2;
    const int mtg0 = blockIdx.y * 8 + wm * 2;
    const int nfl0 = wnn * 8;

    {
        const uint4* src = (const uint4*)(g_wf + (size_t)bx * 16384);
#pragma unroll
        for (int q = 0; q < 16; q++)
            ((uint4*)Bs)[t + q * 256] = __ldg(&src[t + q * 256]);
    }

    float c[2][8][4];
#pragma unroll
    for (int i = 0; i < 2; i++)
#pragma unroll
        for (int j = 0; j < 8; j++)
#pragma unroll
            for (int q = 0; q < 4; q++) c[i][j][q] = 0.0f;

    uint32_t ah[2][2][4];
#pragma unroll
    for (int mt2 = 0; mt2 < 2; mt2++) {
        size_t fi = (((size_t)(mtg0 + mt2) * 16) * 32 + lane) * 4;
        *(uint4*)ah[0][mt2] = __ldcg((const uint4*)&g_af[fi]);
    }
    __syncthreads();

#pragma unroll 2
    for (int ks = 0; ks < 16; ks++) {
        const int cur = ks & 1, nxt = cur ^ 1;
        if (ks < 15) {
#pragma unroll
            for (int mt2 = 0; mt2 < 2; mt2++) {
                size_t fi = (((size_t)(mtg0 + mt2) * 16 + ks + 1) * 32 + lane) * 4;
                *(uint4*)ah[nxt][mt2] = __ldcg((const uint4*)&g_af[fi]);
            }
        }
#pragma unroll
        for (int nf2 = 0; nf2 < 8; nf2++) {
            uint32_t b[2];
            *(uint2*)b = *(const uint2*)&Bs[(((nfl0 + nf2) * 16 + ks) * 32 + lane) * 2];
            mmaf16(c[0][nf2], ah[cur][0], b);
            mmaf16(c[1][nf2], ah[cur][1], b);
        }
    }

    const int gate = bx >> 1;
    const float* __restrict__ bias =
        (gate == 0) ? bfb : (gate == 1) ? bib : (gate == 2) ? bub : bob;
    const int jb = (bx & 1) * 128;
    const int m0 = blockIdx.y * 128;
    const int n0 = bx * 128;
#pragma unroll
    for (int mt2 = 0; mt2 < 2; mt2++) {
#pragma unroll
        for (int nf2 = 0; nf2 < 8; nf2++) {
            int row0 = wm * 32 + mt2 * 16 + (lane >> 2);
            int col0 = wnn * 64 + nf2 * 8 + (lane & 3) * 2;
            float b0 = __ldg(&bias[jb + col0]);
            float b1 = __ldg(&bias[jb + col0 + 1]);
            size_t base = (size_t)(m0 + row0) * N4 + n0 + col0;
            *(float2*)&g_xw[base] =
                make_float2(c[mt2][nf2][0] + b0, c[mt2][nf2][1] + b1);
            *(float2*)&g_xw[base + 8 * N4] =
                make_float2(c[mt2][nf2][2] + b0, c[mt2][nf2][3] + b1);
        }
    }
}

// ---------------------------------------------------------------------------
// Phase 2: persistent, 128 CTAs x 256 thr, clusters of 8 = one batch group.
// R9 structure, single fp16 plane: 32 HMMA/warp/step, 16 A-frag LDG.128,
// half the h-exchange traffic (even lanes store packed pairs).
// ---------------------------------------------------------------------------
__global__ void __cluster_dims__(8, 1, 1) __launch_bounds__(256, 1)
qlstm_steps(const float* __restrict__ c0,
            const float* __restrict__ Wf, const float* __restrict__ Wi,
            const float* __restrict__ Wu, const float* __restrict__ Wo,
            const float* __restrict__ thf, const float* __restrict__ scf,
            const float* __restrict__ thi, const float* __restrict__ sci,
            const float* __restrict__ thu, const float* __restrict__ scu,
            const float* __restrict__ tho, const float* __restrict__ sco,
            float* __restrict__ out)
{
    extern __shared__ char smraw[];
    uint32_t* Bf = (uint32_t*)smraw;               // 16384 words (64 KB)
    float* g_s = (float*)(Bf + 16384);             // [16][132]

    const int cid = blockIdx.x;
    const int bg  = cid >> 3;
    const int jt  = cid & 7;
    const int j0  = jt * 32;

    const int t = threadIdx.x;
    const int lane = t & 31, w = t >> 5;
    const int gate = w >> 1;

    // W -> fragment-major fp16 in SMEM (one-time, single plane)
    {
        const int c = t >> 1;
        const int kb = (t & 1) * 128;
        const int gg = c >> 5;
        const float* __restrict__ Wp = (gg == 0) ? Wf : (gg == 1) ? Wi
                                       : (gg == 2) ? Wu : Wo;
        const float* src = Wp + (size_t)(j0 + (c & 31)) * 512 + 256 + kb;
        const int nf = c >> 3;
        const int lp_base = (c & 7) * 4;
#pragma unroll 8
        for (int q = 0; q < 32; q++) {
            float4 v = *(const float4*)(src + q * 4);
            float f[4] = {v.x, v.y, v.z, v.w};
#pragma unroll
            for (int e = 0; e < 4; e++) {
                int k = kb + q * 4 + e;
                int ks = k >> 4, kk = k & 15;
                int lp = lp_base + ((kk & 7) >> 1);
                int rg = kk >> 3;
                int fi = ((ks * 16 + nf) * 32 + lp) * 2 + rg;
                ((__half*)&Bf[fi])[kk & 1] = __float2half(f[e]);
            }
        }
    }

    const float* __restrict__ thp = (gate == 0) ? thf : (gate == 1) ? thi
                                    : (gate == 2) ? thu : tho;
    const float* __restrict__ scp = (gate == 0) ? scf : (gate == 1) ? sci
                                    : (gate == 2) ? scu : sco;
    float thv[2][2], scv[2][2];
#pragma unroll
    for (int i2 = 0; i2 < 2; i2++) {
        int cc = (2 * w + i2) * 8 + (lane & 3) * 2;
        thv[i2][0] = thp[j0 + (cc & 31)];
        thv[i2][1] = thp[j0 + ((cc + 1) & 31)];
        scv[i2][0] = scp[j0 + (cc & 31)];
        scv[i2][1] = scp[j0 + ((cc + 1) & 31)];
    }
    const float va = (gate == 2) ? 2.0f : 1.0f;
    const float vb = (gate == 2) ? 2.0f : 1.0f;
    const float vc = (gate == 2) ? -1.0f : 0.0f;

    float c_reg[2];
#pragma unroll
    for (int p = 0; p < 2; p++) {
        int s = t + p * 256;
        c_reg[p] = c0[(size_t)(bg * 16 + (s >> 5)) * 256 + j0 + (s & 31)];
    }

    // initial xw prefetch for ts = 0
    float2 xwv[2][2];
#pragma unroll
    for (int rr = 0; rr < 2; rr++) {
        int b = bg * 16 + (lane >> 2) + rr * 8;
#pragma unroll
        for (int i2 = 0; i2 < 2; i2++) {
            int cc = (2 * w + i2) * 8 + (lane & 3) * 2;
            int n = gate * 256 + j0 + (cc & 31);
            xwv[rr][i2] = __ldcg((const float2*)&g_xw[((size_t)b) * N4 + n]);
        }
    }

    __syncthreads();

    for (int ts = 0; ts < SEQ; ts++) {
        const int rp = ts & 1, wp2 = (ts + 1) & 1;
        const bool last = (ts == SEQ - 1);

        // ---- GEMM 16 x 128 x 256: A frags from gmem (L2), single plane ----
        float acc[2][4];
#pragma unroll
        for (int i2 = 0; i2 < 2; i2++)
#pragma unroll
            for (int q = 0; q < 4; q++) acc[i2][q] = 0.0f;

        const uint32_t* __restrict__ fh = g_hf[rp][bg];
#pragma unroll 4
        for (int ks = 0; ks < 16; ks++) {
            uint32_t ah[4];
            *(uint4*)ah = __ldcg((const uint4*)&fh[(ks * 32 + lane) * 4]);
#pragma unroll
            for (int i2 = 0; i2 < 2; i2++) {
                int nf = 2 * w + i2;
                uint32_t b[2];
                *(uint2*)b = *(const uint2*)&Bf[((ks * 16 + nf) * 32 + lane) * 2];
                mmaf16(acc[i2], ah, b);
            }
        }

        // ---- nonlinearities -> g_s ----
#pragma unroll
        for (int i2 = 0; i2 < 2; i2++) {
            int cc = (2 * w + i2) * 8 + (lane & 3) * 2;
#pragma unroll
            for (int rr = 0; rr < 2; rr++) {
                int row = (lane >> 2) + rr * 8;
                float z0 = acc[i2][rr * 2]     + xwv[rr][i2].x;
                float z1 = acc[i2][rr * 2 + 1] + xwv[rr][i2].y;
                float q0 = sigmoidf_(__sinf(z0 * thv[i2][0]) * scv[i2][0]);
                float q1 = sigmoidf_(__sinf(z1 * thv[i2][1]) * scv[i2][1]);
                g_s[row * 132 + cc]     = va * sigmoidf_(vb * q0) + vc;
                g_s[row * 132 + cc + 1] = va * sigmoidf_(vb * q1) + vc;
            }
        }
        __syncthreads();

        // ---- state update + h frag stores (skip stores on last step) ----
        float h_out[2], c_out[2];
#pragma unroll
        for (int p = 0; p < 2; p++) {
            int s = t + p * 256;
            int b_l = s >> 5, jj = s & 31;
            float fv = g_s[b_l * 132 +       jj];
            float iv = g_s[b_l * 132 +  32 + jj];
            float uv = g_s[b_l * 132 +  64 + jj];
            float ov = g_s[b_l * 132 +  96 + jj];
            float cc = fv * c_reg[p] + iv * uv;
            c_reg[p] = cc;
            c_out[p] = cc;
            float h = ov * tanhf_fast(cc);
            h_out[p] = h;

            // pack (jj even, jj odd) fp16 pair; even lane stores the word
            uint32_t mine = (uint32_t)__half_as_ushort(__float2half(h));
            uint32_t peer = __shfl_xor_sync(0xffffffffu, mine, 1);
            if (!last && !(t & 1)) {
                int j = j0 + jj;
                int ks = j >> 4, kk = j & 15;
                int lp = (b_l & 7) * 4 + ((kk & 7) >> 1);
                int rg = ((b_l >> 3) & 1) | ((kk >> 3) << 1);
                int fi = (ks * 32 + lp) * 4 + rg;
                g_hf[wp2][bg][fi] = mine | (peer << 16);
            }
        }

        if (!last) {
            // prefetch xw for ts+1 (recurrence-independent; hides under barrier)
#pragma unroll
            for (int rr = 0; rr < 2; rr++) {
                int b = bg * 16 + (lane >> 2) + rr * 8;
#pragma unroll
                for (int i2 = 0; i2 < 2; i2++) {
                    int cc = (2 * w + i2) * 8 + (lane & 3) * 2;
                    int n = gate * 256 + j0 + (cc & 31);
                    xwv[rr][i2] = __ldcg((const float2*)
                        &g_xw[((size_t)(ts + 1) * BATCH + b) * N4 + n]);
                }
            }
            // release/acquire ordering for the gmem frag exchange
            asm volatile("barrier.cluster.arrive.aligned;" ::: "memory");
            asm volatile("barrier.cluster.wait.aligned;" ::: "memory");
        }

        // ---- out stores (after barrier: off the recurrence critical path) ----
#pragma unroll
        for (int p = 0; p < 2; p++) {
            int s = t + p * 256;
            int b = bg * 16 + (s >> 5);
            int j = j0 + (s & 31);
            out[((size_t)ts * BATCH + b) * HID + j] = h_out[p];
            if (last) {
                size_t sidx = (size_t)b * HID + j;
                out[OUT_SEQ_ELEMS + sidx] = h_out[p];
                out[OUT_SEQ_ELEMS + (size_t)BATCH * HID + sidx] = c_out[p];
            }
        }
    }
}

// ---------------------------------------------------------------------------
extern "C" void kernel_launch(void* const* d_in, const int* in_sizes, int n_in,
                              void* d_out, int out_size)
{
    (void)in_sizes; (void)n_in; (void)out_size;
    const float* inputs = (const float*)d_in[0];
    const float* h0  = (const float*)d_in[1];
    const float* c0  = (const float*)d_in[2];
    const float* Wf  = (const float*)d_in[3];
    const float* bf  = (const float*)d_in[4];
    const float* thf = (const float*)d_in[5];
    const float* scf = (const float*)d_in[6];
    const float* Wi  = (const float*)d_in[7];
    const float* bi  = (const float*)d_in[8];
    const float* thi = (const float*)d_in[9];
    const float* sci = (const float*)d_in[10];
    const float* Wu  = (const float*)d_in[11];
    const float* bu  = (const float*)d_in[12];
    const float* thu = (const float*)d_in[13];
    const float* scu = (const float*)d_in[14];
    const float* Wo  = (const float*)d_in[15];
    const float* bo  = (const float*)d_in[16];
    const float* tho = (const float*)d_in[17];
    const float* sco = (const float*)d_in[18];
    float* out = (float*)d_out;

    // fused conversions (X A-frags + W B-frags + h0 frags) in one launch
    conv_all<<<4384, 256>>>(inputs, Wf, Wi, Wu, Wo, h0);

    dim3 g1(8, GM_M / 128);
    xw_mma<<<g1, 256>>>(bf, bi, bu, bo);

    const int smem2 = 16384 * 4 + 16 * 132 * 4;   // 65536 + 8448
    cudaFuncSetAttribute(qlstm_steps, cudaFuncAttributeMaxDynamicSharedMemorySize, smem2);
    qlstm_steps<<<128, 256, smem2>>>(c0, Wf, Wi, Wu, Wo,
                                     thf, scf, thi, sci, thu, scu, tho, sco,
                                     out);
}

// round 15
// speedup vs baseline: 1.9432x; 1.0241x over previous
#include <cuda_runtime.h>
#include <cuda_fp16.h>
#include <cstdint>

#define SEQ 512
#define BATCH 256
#define HID 256
#define N4 1024
#define GM_M (SEQ * BATCH)                           // 131072 rows
#define OUT_SEQ_ELEMS ((size_t)SEQ * BATCH * HID)    // 33554432

// scratch
__device__ __half g_xw[(size_t)SEQ * BATCH * N4];                // 256 MB (fp16)

// A fragments of X (single fp16 plane): [mt 8192][ks 16][lane 32][reg 4] uint32
__device__ uint32_t g_af[(size_t)8192 * 16 * 32 * 4];            // 64 MB
// B fragments of Wx (single fp16 plane): [nf 128][ks 16][lane 32][reg 2]
__device__ uint32_t g_wf[128 * 16 * 32 * 2];                     // 512 KB

// h fragment buffers (single fp16 plane): [parity][bg][frag words]
#define FRAG_WORDS (16 * 32 * 4)
__device__ uint32_t g_hf[2][16][FRAG_WORDS];

// ---------------------------------------------------------------------------
// helpers
// ---------------------------------------------------------------------------
__device__ __forceinline__ float sigmoidf_(float x) {
    return __fdividef(1.0f, 1.0f + __expf(-x));
}
__device__ __forceinline__ float tanhf_fast(float x) {
    return 2.0f * sigmoidf_(2.0f * x) - 1.0f;
}
__device__ __forceinline__ uint32_t packh2(__half a, __half b) {
    return (uint32_t)__half_as_ushort(a) | ((uint32_t)__half_as_ushort(b) << 16);
}
__device__ __forceinline__ uint32_t pack_hi2(float a, float b) {
    return packh2(__float2half(a), __float2half(b));
}

// legacy tensor-core mma fp16 (compute_80 PTX — compiles under compute_103)
__device__ __forceinline__ void mmaf16(float* c, const uint32_t* a, const uint32_t* b) {
    asm volatile(
        "mma.sync.aligned.m16n8k16.row.col.f32.f16.f16.f32 "
        "{%0,%1,%2,%3}, {%4,%5,%6,%7}, {%8,%9}, {%0,%1,%2,%3};"
        : "+f"(c[0]), "+f"(c[1]), "+f"(c[2]), "+f"(c[3])
        : "r"(a[0]), "r"(a[1]), "r"(a[2]), "r"(a[3]), "r"(b[0]), "r"(b[1]));
}

// ---------------------------------------------------------------------------
// conv_all: one launch, block-range dispatch.
//   blocks [0, 4096)        : X fp32 -> A-fragment fp16 plane
//   blocks [4096, 4128)     : Wx fp32 -> fp16 B-fragment plane
//   blocks [4128, 4384)     : h0 -> fragment buffer parity 0
// ---------------------------------------------------------------------------
__global__ void __launch_bounds__(256)
conv_all(const float* __restrict__ X,
         const float* __restrict__ Wf, const float* __restrict__ Wi,
         const float* __restrict__ Wu, const float* __restrict__ Wo,
         const float* __restrict__ h0) {
    const int bid = blockIdx.x;
    const int lane = threadIdx.x & 31;

    if (bid < 4096) {
        // ---- conv_x ----
        const int wg = (bid * 256 + threadIdx.x) >> 5;  // 0..32767
        const int r7 = lane >> 2;
        const int kb = (lane & 3) * 2;
#pragma unroll
        for (int q = 0; q < 4; q++) {
            int task = wg * 4 + q;                 // mt*16 + ks
            int mt = task >> 4, ks = task & 15;
            const float* base = X + (size_t)(mt * 16 + r7) * 256 + ks * 16 + kb;
            float2 v00 = *(const float2*)(base);
            float2 v01 = *(const float2*)(base + 8);
            float2 v10 = *(const float2*)(base + 8 * 256);
            float2 v11 = *(const float2*)(base + 8 * 256 + 8);
            uint4 hi;
            hi.x = pack_hi2(v00.x, v00.y);
            hi.y = pack_hi2(v10.x, v10.y);
            hi.z = pack_hi2(v01.x, v01.y);
            hi.w = pack_hi2(v11.x, v11.y);
            size_t fi = ((size_t)task * 32 + lane) * 4;
            *(uint4*)&g_af[fi] = hi;
        }
    } else if (bid < 4128) {
        // ---- conv_w ----
        const int wg = ((bid - 4096) * 256 + threadIdx.x) >> 5;  // 0..255
        const int n7 = lane >> 2;
        const int kb = (lane & 3) * 2;
#pragma unroll
        for (int q = 0; q < 8; q++) {
            int task = wg * 8 + q;                 // nf*16 + ks
            int nf = task >> 4, ks = task & 15;
            int n = nf * 8 + n7;
            int gate = n >> 8, j = n & 255;
            const float* Wp = (gate == 0) ? Wf : (gate == 1) ? Wi : (gate == 2) ? Wu : Wo;
            const float* base = Wp + (size_t)j * 512 + ks * 16 + kb;
            float2 v0 = *(const float2*)(base);
            float2 v1 = *(const float2*)(base + 8);
            uint2 hi;
            hi.x = pack_hi2(v0.x, v0.y);
            hi.y = pack_hi2(v1.x, v1.y);
            size_t fi = ((size_t)task * 32 + lane) * 2;
            *(uint2*)&g_wf[fi] = hi;
        }
    } else {
        // ---- conv_h0 ----
        int idx = (bid - 4128) * 256 + threadIdx.x;    // 65536
        int b = idx >> 8, j = idx & 255;
        float v = h0[idx];
        __half hh = __float2half(v);
        int bg = b >> 4, b_l = b & 15;
        int ks = j >> 4, kk = j & 15;
        int lp = (b_l & 7) * 4 + ((kk & 7) >> 1);
        int reg = ((b_l >> 3) & 1) | ((kk >> 3) << 1);
        int fi = (ks * 32 + lp) * 4 + reg;
        ((__half*)&g_hf[0][bg][fi])[kk & 1] = hh;
    }
}

// ---------------------------------------------------------------------------
// Phase 1: XW = X @ Wx^T + b. Single fp16 plane; fp16 output (halved writes).
// ---------------------------------------------------------------------------
__global__ void __launch_bounds__(256, 2)
xw_mma(const float* __restrict__ bfb, const float* __restrict__ bib,
       const float* __restrict__ bub, const float* __restrict__ bob)
{
    __shared__ uint32_t Bs[16 * 16 * 32 * 2];     // 64 KB

    const int t = threadIdx.x;
    const int lane = t & 31, wid = t >> 5;
    const int bx = blockIdx.x;
    const int wm = wid & 3;
    const int wnn = wid >> 2;
    const int mtg0 = blockIdx.y * 8 + wm * 2;
    const int nfl0 = wnn * 8;

    {
        const uint4* src = (const uint4*)(g_wf + (size_t)bx * 16384);
#pragma unroll
        for (int q = 0; q < 16; q++)
            ((uint4*)Bs)[t + q * 256] = __ldg(&src[t + q * 256]);
    }

    float c[2][8][4];
#pragma unroll
    for (int i = 0; i < 2; i++)
#pragma unroll
        for (int j = 0; j < 8; j++)
#pragma unroll
            for (int q = 0; q < 4; q++) c[i][j][q] = 0.0f;

    uint32_t ah[2][2][4];
#pragma unroll
    for (int mt2 = 0; mt2 < 2; mt2++) {
        size_t fi = (((size_t)(mtg0 + mt2) * 16) * 32 + lane) * 4;
        *(uint4*)ah[0][mt2] = __ldcg((const uint4*)&g_af[fi]);
    }
    __syncthreads();

#pragma unroll 2
    for (int ks = 0; ks < 16; ks++) {
        const int cur = ks & 1, nxt = cur ^ 1;
        if (ks < 15) {
#pragma unroll
            for (int mt2 = 0; mt2 < 2; mt2++) {
                size_t fi = (((size_t)(mtg0 + mt2) * 16 + ks + 1) * 32 + lane) * 4;
                *(uint4*)ah[nxt][mt2] = __ldcg((const uint4*)&g_af[fi]);
            }
        }
#pragma unroll
        for (int nf2 = 0; nf2 < 8; nf2++) {
            uint32_t b[2];
            *(uint2*)b = *(const uint2*)&Bs[(((nfl0 + nf2) * 16 + ks) * 32 + lane) * 2];
            mmaf16(c[0][nf2], ah[cur][0], b);
            mmaf16(c[1][nf2], ah[cur][1], b);
        }
    }

    const int gate = bx >> 1;
    const float* __restrict__ bias =
        (gate == 0) ? bfb : (gate == 1) ? bib : (gate == 2) ? bub : bob;
    const int jb = (bx & 1) * 128;
    const int m0 = blockIdx.y * 128;
    const int n0 = bx * 128;
#pragma unroll
    for (int mt2 = 0; mt2 < 2; mt2++) {
#pragma unroll
        for (int nf2 = 0; nf2 < 8; nf2++) {
            int row0 = wm * 32 + mt2 * 16 + (lane >> 2);
            int col0 = wnn * 64 + nf2 * 8 + (lane & 3) * 2;
            float b0 = __ldg(&bias[jb + col0]);
            float b1 = __ldg(&bias[jb + col0 + 1]);
            size_t base = (size_t)(m0 + row0) * N4 + n0 + col0;
            *(uint32_t*)&g_xw[base] =
                pack_hi2(c[mt2][nf2][0] + b0, c[mt2][nf2][1] + b1);
            *(uint32_t*)&g_xw[base + 8 * N4] =
                pack_hi2(c[mt2][nf2][2] + b0, c[mt2][nf2][3] + b1);
        }
    }
}

// ---------------------------------------------------------------------------
// Phase 2: persistent, 128 CTAs x 256 thr, clusters of 8 = one batch group.
// R9 structure, single fp16 plane; HMMA acc split by ks parity (depth 16->8);
// xw read as fp16 (halved prefetch traffic).
// ---------------------------------------------------------------------------
__global__ void __cluster_dims__(8, 1, 1) __launch_bounds__(256, 1)
qlstm_steps(const float* __restrict__ c0,
            const float* __restrict__ Wf, const float* __restrict__ Wi,
            const float* __restrict__ Wu, const float* __restrict__ Wo,
            const float* __restrict__ thf, const float* __restrict__ scf,
            const float* __restrict__ thi, const float* __restrict__ sci,
            const float* __restrict__ thu, const float* __restrict__ scu,
            const float* __restrict__ tho, const float* __restrict__ sco,
            float* __restrict__ out)
{
    extern __shared__ char smraw[];
    uint32_t* Bf = (uint32_t*)smraw;               // 16384 words (64 KB)
    float* g_s = (float*)(Bf + 16384);             // [16][132]

    const int cid = blockIdx.x;
    const int bg  = cid >> 3;
    const int jt  = cid & 7;
    const int j0  = jt * 32;

    const int t = threadIdx.x;
    const int lane = t & 31, w = t >> 5;
    const int gate = w >> 1;

    // W -> fragment-major fp16 in SMEM (one-time, single plane)
    {
        const int c = t >> 1;
        const int kb = (t & 1) * 128;
        const int gg = c >> 5;
        const float* __restrict__ Wp = (gg == 0) ? Wf : (gg == 1) ? Wi
                                       : (gg == 2) ? Wu : Wo;
        const float* src = Wp + (size_t)(j0 + (c & 31)) * 512 + 256 + kb;
        const int nf = c >> 3;
        const int lp_base = (c & 7) * 4;
#pragma unroll 8
        for (int q = 0; q < 32; q++) {
            float4 v = *(const float4*)(src + q * 4);
            float f[4] = {v.x, v.y, v.z, v.w};
#pragma unroll
            for (int e = 0; e < 4; e++) {
                int k = kb + q * 4 + e;
                int ks = k >> 4, kk = k & 15;
                int lp = lp_base + ((kk & 7) >> 1);
                int rg = kk >> 3;
                int fi = ((ks * 16 + nf) * 32 + lp) * 2 + rg;
                ((__half*)&Bf[fi])[kk & 1] = __float2half(f[e]);
            }
        }
    }

    const float* __restrict__ thp = (gate == 0) ? thf : (gate == 1) ? thi
                                    : (gate == 2) ? thu : tho;
    const float* __restrict__ scp = (gate == 0) ? scf : (gate == 1) ? sci
                                    : (gate == 2) ? scu : sco;
    float thv[2][2], scv[2][2];
#pragma unroll
    for (int i2 = 0; i2 < 2; i2++) {
        int cc = (2 * w + i2) * 8 + (lane & 3) * 2;
        thv[i2][0] = thp[j0 + (cc & 31)];
        thv[i2][1] = thp[j0 + ((cc + 1) & 31)];
        scv[i2][0] = scp[j0 + (cc & 31)];
        scv[i2][1] = scp[j0 + ((cc + 1) & 31)];
    }
    const float va = (gate == 2) ? 2.0f : 1.0f;
    const float vb = (gate == 2) ? 2.0f : 1.0f;
    const float vc = (gate == 2) ? -1.0f : 0.0f;

    float c_reg[2];
#pragma unroll
    for (int p = 0; p < 2; p++) {
        int s = t + p * 256;
        c_reg[p] = c0[(size_t)(bg * 16 + (s >> 5)) * 256 + j0 + (s & 31)];
    }

    // initial xw prefetch for ts = 0 (fp16 pair per thread position)
    uint32_t xwu[2][2];
#pragma unroll
    for (int rr = 0; rr < 2; rr++) {
        int b = bg * 16 + (lane >> 2) + rr * 8;
#pragma unroll
        for (int i2 = 0; i2 < 2; i2++) {
            int cc = (2 * w + i2) * 8 + (lane & 3) * 2;
            int n = gate * 256 + j0 + (cc & 31);
            xwu[rr][i2] = __ldcg((const uint32_t*)&g_xw[(size_t)b * N4 + n]);
        }
    }

    __syncthreads();

    for (int ts = 0; ts < SEQ; ts++) {
        const int rp = ts & 1, wp2 = (ts + 1) & 1;
        const bool last = (ts == SEQ - 1);

        // ---- GEMM 16 x 128 x 256: acc split by ks parity (chain depth 8) ----
        float acca[2][4], accb[2][4];
#pragma unroll
        for (int i2 = 0; i2 < 2; i2++)
#pragma unroll
            for (int q = 0; q < 4; q++) { acca[i2][q] = 0.0f; accb[i2][q] = 0.0f; }

        const uint32_t* __restrict__ fh = g_hf[rp][bg];
#pragma unroll 4
        for (int ks = 0; ks < 16; ks++) {
            uint32_t ah[4];
            *(uint4*)ah = __ldcg((const uint4*)&fh[(ks * 32 + lane) * 4]);
            float* acc0 = (ks & 1) ? accb[0] : acca[0];
            float* acc1 = (ks & 1) ? accb[1] : acca[1];
            uint32_t b0[2], b1[2];
            *(uint2*)b0 = *(const uint2*)&Bf[((ks * 16 + 2 * w) * 32 + lane) * 2];
            *(uint2*)b1 = *(const uint2*)&Bf[((ks * 16 + 2 * w + 1) * 32 + lane) * 2];
            mmaf16(acc0, ah, b0);
            mmaf16(acc1, ah, b1);
        }

        // ---- nonlinearities -> g_s ----
#pragma unroll
        for (int i2 = 0; i2 < 2; i2++) {
            int cc = (2 * w + i2) * 8 + (lane & 3) * 2;
#pragma unroll
            for (int rr = 0; rr < 2; rr++) {
                int row = (lane >> 2) + rr * 8;
                float2 xv = __half22float2(*(const __half2*)&xwu[rr][i2]);
                float z0 = acca[i2][rr * 2]     + accb[i2][rr * 2]     + xv.x;
                float z1 = acca[i2][rr * 2 + 1] + accb[i2][rr * 2 + 1] + xv.y;
                float q0 = sigmoidf_(__sinf(z0 * thv[i2][0]) * scv[i2][0]);
                float q1 = sigmoidf_(__sinf(z1 * thv[i2][1]) * scv[i2][1]);
                g_s[row * 132 + cc]     = va * sigmoidf_(vb * q0) + vc;
                g_s[row * 132 + cc + 1] = va * sigmoidf_(vb * q1) + vc;
            }
        }
        __syncthreads();

        // ---- state update + h frag stores (skip stores on last step) ----
        float h_out[2], c_out[2];
#pragma unroll
        for (int p = 0; p < 2; p++) {
            int s = t + p * 256;
            int b_l = s >> 5, jj = s & 31;
            float fv = g_s[b_l * 132 +       jj];
            float iv = g_s[b_l * 132 +  32 + jj];
            float uv = g_s[b_l * 132 +  64 + jj];
            float ov = g_s[b_l * 132 +  96 + jj];
            float cc = fv * c_reg[p] + iv * uv;
            c_reg[p] = cc;
            c_out[p] = cc;
            float h = ov * tanhf_fast(cc);
            h_out[p] = h;

            // pack (jj even, jj odd) fp16 pair; even lane stores the word
            uint32_t mine = (uint32_t)__half_as_ushort(__float2half(h));
            uint32_t peer = __shfl_xor_sync(0xffffffffu, mine, 1);
            if (!last && !(t & 1)) {
                int j = j0 + jj;
                int ks = j >> 4, kk = j & 15;
                int lp = (b_l & 7) * 4 + ((kk & 7) >> 1);
                int rg = ((b_l >> 3) & 1) | ((kk >> 3) << 1);
                int fi = (ks * 32 + lp) * 4 + rg;
                g_hf[wp2][bg][fi] = mine | (peer << 16);
            }
        }

        if (!last) {
            // prefetch xw for ts+1 (recurrence-independent; hides under barrier)
#pragma unroll
            for (int rr = 0; rr < 2; rr++) {
                int b = bg * 16 + (lane >> 2) + rr * 8;
#pragma unroll
                for (int i2 = 0; i2 < 2; i2++) {
                    int cc = (2 * w + i2) * 8 + (lane & 3) * 2;
                    int n = gate * 256 + j0 + (cc & 31);
                    xwu[rr][i2] = __ldcg((const uint32_t*)
                        &g_xw[((size_t)(ts + 1) * BATCH + b) * N4 + n]);
                }
            }
            // release/acquire ordering for the gmem frag exchange
            asm volatile("barrier.cluster.arrive.aligned;" ::: "memory");
            asm volatile("barrier.cluster.wait.aligned;" ::: "memory");
        }

        // ---- out stores (after barrier: off the recurrence critical path) ----
#pragma unroll
        for (int p = 0; p < 2; p++) {
            int s = t + p * 256;
            int b = bg * 16 + (s >> 5);
            int j = j0 + (s & 31);
            out[((size_t)ts * BATCH + b) * HID + j] = h_out[p];
            if (last) {
                size_t sidx = (size_t)b * HID + j;
                out[OUT_SEQ_ELEMS + sidx] = h_out[p];
                out[OUT_SEQ_ELEMS + (size_t)BATCH * HID + sidx] = c_out[p];
            }
        }
    }
}

// ---------------------------------------------------------------------------
extern "C" void kernel_launch(void* const* d_in, const int* in_sizes, int n_in,
                              void* d_out, int out_size)
{
    (void)in_sizes; (void)n_in; (void)out_size;
    const float* inputs = (const float*)d_in[0];
    const float* h0  = (const float*)d_in[1];
    const float* c0  = (const float*)d_in[2];
    const float* Wf  = (const float*)d_in[3];
    const float* bf  = (const float*)d_in[4];
    const float* thf = (const float*)d_in[5];
    const float* scf = (const float*)d_in[6];
    const float* Wi  = (const float*)d_in[7];
    const float* bi  = (const float*)d_in[8];
    const float* thi = (const float*)d_in[9];
    const float* sci = (const float*)d_in[10];
    const float* Wu  = (const float*)d_in[11];
    const float* bu  = (const float*)d_in[12];
    const float* thu = (const float*)d_in[13];
    const float* scu = (const float*)d_in[14];
    const float* Wo  = (const float*)d_in[15];
    const float* bo  = (const float*)d_in[16];
    const float* tho = (const float*)d_in[17];
    const float* sco = (const float*)d_in[18];
    float* out = (float*)d_out;

    // fused conversions (X A-frags + W B-frags + h0 frags) in one launch
    conv_all<<<4384, 256>>>(inputs, Wf, Wi, Wu, Wo, h0);

    dim3 g1(8, GM_M / 128);
    xw_mma<<<g1, 256>>>(bf, bi, bu, bo);

    const int smem2 = 16384 * 4 + 16 * 132 * 4;   // 65536 + 8448
    cudaFuncSetAttribute(qlstm_steps, cudaFuncAttributeMaxDynamicSharedMemorySize, smem2);
    qlstm_steps<<<128, 256, smem2>>>(c0, Wf, Wi, Wu, Wo,
                                     thf, scf, thi, sci, thu, scu, tho, sco,
                                     out);
}

// round 16
// speedup vs baseline: 2.1951x; 1.1296x over previous
#include <cuda_runtime.h>
#include <cuda_fp16.h>
#include <cstdint>

#define SEQ 512
#define BATCH 256
#define HID 256
#define N4 1024
#define GM_M (SEQ * BATCH)                           // 131072 rows
#define OUT_SEQ_ELEMS ((size_t)SEQ * BATCH * HID)    // 33554432

// scratch
__device__ __half g_xw[(size_t)SEQ * BATCH * N4];                // 256 MB (fp16)

// A fragments of X (single fp16 plane): [mt 8192][ks 16][lane 32][reg 4] uint32
__device__ uint32_t g_af[(size_t)8192 * 16 * 32 * 4];            // 64 MB
// B fragments of Wx (single fp16 plane): [nf 128][ks 16][lane 32][reg 2]
__device__ uint32_t g_wf[128 * 16 * 32 * 2];                     // 512 KB

// h fragment buffers (single fp16 plane, M=8 tiles -> 2 regs/lane):
// [parity][bg 32][ (ks*32 + lp)*2 + rg ] uint32
#define FRAG_WORDS (16 * 32 * 2)
__device__ uint32_t g_hf[2][32][FRAG_WORDS];

// ---------------------------------------------------------------------------
// helpers
// ---------------------------------------------------------------------------
__device__ __forceinline__ float sigmoidf_(float x) {
    return __fdividef(1.0f, 1.0f + __expf(-x));
}
__device__ __forceinline__ float tanhf_fast(float x) {
    return 2.0f * sigmoidf_(2.0f * x) - 1.0f;
}
__device__ __forceinline__ uint32_t packh2(__half a, __half b) {
    return (uint32_t)__half_as_ushort(a) | ((uint32_t)__half_as_ushort(b) << 16);
}
__device__ __forceinline__ uint32_t pack_hi2(float a, float b) {
    return packh2(__float2half(a), __float2half(b));
}

// legacy tensor-core mma fp16 (compute_80 PTX — compiles under compute_103)
__device__ __forceinline__ void mmaf16(float* c, const uint32_t* a, const uint32_t* b) {
    asm volatile(
        "mma.sync.aligned.m16n8k16.row.col.f32.f16.f16.f32 "
        "{%0,%1,%2,%3}, {%4,%5,%6,%7}, {%8,%9}, {%0,%1,%2,%3};"
        : "+f"(c[0]), "+f"(c[1]), "+f"(c[2]), "+f"(c[3])
        : "r"(a[0]), "r"(a[1]), "r"(a[2]), "r"(a[3]), "r"(b[0]), "r"(b[1]));
}

// ---------------------------------------------------------------------------
// conv_all: one launch, block-range dispatch.
//   blocks [0, 4096)        : X fp32 -> A-fragment fp16 plane
//   blocks [4096, 4128)     : Wx fp32 -> fp16 B-fragment plane
//   blocks [4128, 4384)     : h0 -> fragment buffer parity 0 (M=8 layout)
// ---------------------------------------------------------------------------
__global__ void __launch_bounds__(256)
conv_all(const float* __restrict__ X,
         const float* __restrict__ Wf, const float* __restrict__ Wi,
         const float* __restrict__ Wu, const float* __restrict__ Wo,
         const float* __restrict__ h0) {
    const int bid = blockIdx.x;
    const int lane = threadIdx.x & 31;

    if (bid < 4096) {
        // ---- conv_x ----
        const int wg = (bid * 256 + threadIdx.x) >> 5;  // 0..32767
        const int r7 = lane >> 2;
        const int kb = (lane & 3) * 2;
#pragma unroll
        for (int q = 0; q < 4; q++) {
            int task = wg * 4 + q;                 // mt*16 + ks
            int mt = task >> 4, ks = task & 15;
            const float* base = X + (size_t)(mt * 16 + r7) * 256 + ks * 16 + kb;
            float2 v00 = *(const float2*)(base);
            float2 v01 = *(const float2*)(base + 8);
            float2 v10 = *(const float2*)(base + 8 * 256);
            float2 v11 = *(const float2*)(base + 8 * 256 + 8);
            uint4 hi;
            hi.x = pack_hi2(v00.x, v00.y);
            hi.y = pack_hi2(v10.x, v10.y);
            hi.z = pack_hi2(v01.x, v01.y);
            hi.w = pack_hi2(v11.x, v11.y);
            size_t fi = ((size_t)task * 32 + lane) * 4;
            *(uint4*)&g_af[fi] = hi;
        }
    } else if (bid < 4128) {
        // ---- conv_w ----
        const int wg = ((bid - 4096) * 256 + threadIdx.x) >> 5;  // 0..255
        const int n7 = lane >> 2;
        const int kb = (lane & 3) * 2;
#pragma unroll
        for (int q = 0; q < 8; q++) {
            int task = wg * 8 + q;                 // nf*16 + ks
            int nf = task >> 4, ks = task & 15;
            int n = nf * 8 + n7;
            int gate = n >> 8, j = n & 255;
            const float* Wp = (gate == 0) ? Wf : (gate == 1) ? Wi : (gate == 2) ? Wu : Wo;
            const float* base = Wp + (size_t)j * 512 + ks * 16 + kb;
            float2 v0 = *(const float2*)(base);
            float2 v1 = *(const float2*)(base + 8);
            uint2 hi;
            hi.x = pack_hi2(v0.x, v0.y);
            hi.y = pack_hi2(v1.x, v1.y);
            size_t fi = ((size_t)task * 32 + lane) * 2;
            *(uint2*)&g_wf[fi] = hi;
        }
    } else {
        // ---- conv_h0 (M=8 layout) ----
        int idx = (bid - 4128) * 256 + threadIdx.x;    // 65536
        int b = idx >> 8, j = idx & 255;
        float v = h0[idx];
        __half hh = __float2half(v);
        int bg = b >> 3, b_l = b & 7;
        int ks = j >> 4, kk = j & 15;
        int lp = b_l * 4 + ((kk & 7) >> 1);
        int rg = kk >> 3;
        int fi = (ks * 32 + lp) * 2 + rg;
        ((__half*)&g_hf[0][bg][fi])[kk & 1] = hh;
    }
}

// ---------------------------------------------------------------------------
// Phase 1: XW = X @ Wx^T + b. Single fp16 plane; fp16 output. (unchanged R15)
// ---------------------------------------------------------------------------
__global__ void __launch_bounds__(256, 2)
xw_mma(const float* __restrict__ bfb, const float* __restrict__ bib,
       const float* __restrict__ bub, const float* __restrict__ bob)
{
    __shared__ uint32_t Bs[16 * 16 * 32 * 2];     // 64 KB

    const int t = threadIdx.x;
    const int lane = t & 31, wid = t >> 5;
    const int bx = blockIdx.x;
    const int wm = wid & 3;
    const int wnn = wid >> 2;
    const int mtg0 = blockIdx.y * 8 + wm * 2;
    const int nfl0 = wnn * 8;

    {
        const uint4* src = (const uint4*)(g_wf + (size_t)bx * 16384);
#pragma unroll
        for (int q = 0; q < 16; q++)
            ((uint4*)Bs)[t + q * 256] = __ldg(&src[t + q * 256]);
    }

    float c[2][8][4];
#pragma unroll
    for (int i = 0; i < 2; i++)
#pragma unroll
        for (int j = 0; j < 8; j++)
#pragma unroll
            for (int q = 0; q < 4; q++) c[i][j][q] = 0.0f;

    uint32_t ah[2][2][4];
#pragma unroll
    for (int mt2 = 0; mt2 < 2; mt2++) {
        size_t fi = (((size_t)(mtg0 + mt2) * 16) * 32 + lane) * 4;
        *(uint4*)ah[0][mt2] = __ldcg((const uint4*)&g_af[fi]);
    }
    __syncthreads();

#pragma unroll 2
    for (int ks = 0; ks < 16; ks++) {
        const int cur = ks & 1, nxt = cur ^ 1;
        if (ks < 15) {
#pragma unroll
            for (int mt2 = 0; mt2 < 2; mt2++) {
                size_t fi = (((size_t)(mtg0 + mt2) * 16 + ks + 1) * 32 + lane) * 4;
                *(uint4*)ah[nxt][mt2] = __ldcg((const uint4*)&g_af[fi]);
            }
        }
#pragma unroll
        for (int nf2 = 0; nf2 < 8; nf2++) {
            uint32_t b[2];
            *(uint2*)b = *(const uint2*)&Bs[(((nfl0 + nf2) * 16 + ks) * 32 + lane) * 2];
            mmaf16(c[0][nf2], ah[cur][0], b);
            mmaf16(c[1][nf2], ah[cur][1], b);
        }
    }

    const int gate = bx >> 1;
    const float* __restrict__ bias =
        (gate == 0) ? bfb : (gate == 1) ? bib : (gate == 2) ? bub : bob;
    const int jb = (bx & 1) * 128;
    const int m0 = blockIdx.y * 128;
    const int n0 = bx * 128;
#pragma unroll
    for (int mt2 = 0; mt2 < 2; mt2++) {
#pragma unroll
        for (int nf2 = 0; nf2 < 8; nf2++) {
            int row0 = wm * 32 + mt2 * 16 + (lane >> 2);
            int col0 = wnn * 64 + nf2 * 8 + (lane & 3) * 2;
            float b0 = __ldg(&bias[jb + col0]);
            float b1 = __ldg(&bias[jb + col0 + 1]);
            size_t base = (size_t)(m0 + row0) * N4 + n0 + col0;
            *(uint32_t*)&g_xw[base] =
                pack_hi2(c[mt2][nf2][0] + b0, c[mt2][nf2][1] + b1);
            *(uint32_t*)&g_xw[base + 8 * N4] =
                pack_hi2(c[mt2][nf2][2] + b0, c[mt2][nf2][3] + b1);
        }
    }
}

// ---------------------------------------------------------------------------
// Phase 2: persistent, 256 CTAs x 256 thr, 32 independent clusters of 8.
// Each CTA: 8 batches (bg = cid>>3, 0..31) x 32 j x 4 gates. 2 CTAs/SM
// co-resident: while one cluster waits on barrier/L2, the other computes.
// MMA m16 uses rows 0-7 (a1=a3=0); one state per thread.
// ---------------------------------------------------------------------------
__global__ void __cluster_dims__(8, 1, 1) __launch_bounds__(256, 2)
qlstm_steps(const float* __restrict__ c0,
            const float* __restrict__ Wf, const float* __restrict__ Wi,
            const float* __restrict__ Wu, const float* __restrict__ Wo,
            const float* __restrict__ thf, const float* __restrict__ scf,
            const float* __restrict__ thi, const float* __restrict__ sci,
            const float* __restrict__ thu, const float* __restrict__ scu,
            const float* __restrict__ tho, const float* __restrict__ sco,
            float* __restrict__ out)
{
    extern __shared__ char smraw[];
    uint32_t* Bf = (uint32_t*)smraw;               // 16384 words (64 KB)
    float* g_s = (float*)(Bf + 16384);             // [8][132]

    const int cid = blockIdx.x;                    // 0..255
    const int bg  = cid >> 3;                      // 0..31 (8 batches each)
    const int jt  = cid & 7;
    const int j0  = jt * 32;

    const int t = threadIdx.x;
    const int lane = t & 31, w = t >> 5;
    const int gate = w >> 1;

    // W -> fragment-major fp16 in SMEM (one-time, single plane)
    {
        const int c = t >> 1;
        const int kb = (t & 1) * 128;
        const int gg = c >> 5;
        const float* __restrict__ Wp = (gg == 0) ? Wf : (gg == 1) ? Wi
                                       : (gg == 2) ? Wu : Wo;
        const float* src = Wp + (size_t)(j0 + (c & 31)) * 512 + 256 + kb;
        const int nf = c >> 3;
        const int lp_base = (c & 7) * 4;
#pragma unroll 8
        for (int q = 0; q < 32; q++) {
            float4 v = *(const float4*)(src + q * 4);
            float f[4] = {v.x, v.y, v.z, v.w};
#pragma unroll
            for (int e = 0; e < 4; e++) {
                int k = kb + q * 4 + e;
                int ks = k >> 4, kk = k & 15;
                int lp = lp_base + ((kk & 7) >> 1);
                int rg = kk >> 3;
                int fi = ((ks * 16 + nf) * 32 + lp) * 2 + rg;
                ((__half*)&Bf[fi])[kk & 1] = __float2half(f[e]);
            }
        }
    }

    const float* __restrict__ thp = (gate == 0) ? thf : (gate == 1) ? thi
                                    : (gate == 2) ? thu : tho;
    const float* __restrict__ scp = (gate == 0) ? scf : (gate == 1) ? sci
                                    : (gate == 2) ? scu : sco;
    float thv[2][2], scv[2][2];
#pragma unroll
    for (int i2 = 0; i2 < 2; i2++) {
        int cc = (2 * w + i2) * 8 + (lane & 3) * 2;
        thv[i2][0] = thp[j0 + (cc & 31)];
        thv[i2][1] = thp[j0 + ((cc + 1) & 31)];
        scv[i2][0] = scp[j0 + (cc & 31)];
        scv[i2][1] = scp[j0 + ((cc + 1) & 31)];
    }
    const float va = (gate == 2) ? 2.0f : 1.0f;
    const float vb = (gate == 2) ? 2.0f : 1.0f;
    const float vc = (gate == 2) ? -1.0f : 0.0f;

    // one state per thread: b_l = t>>5, jj = t&31
    const int b_l = t >> 5, jj = t & 31;
    float c_reg = c0[(size_t)(bg * 8 + b_l) * 256 + j0 + jj];

    // initial xw prefetch for ts = 0 (row = lane>>2, 2 nf cols)
    uint32_t xwu[2];
    {
        int b = bg * 8 + (lane >> 2);
#pragma unroll
        for (int i2 = 0; i2 < 2; i2++) {
            int cc = (2 * w + i2) * 8 + (lane & 3) * 2;
            int n = gate * 256 + j0 + (cc & 31);
            xwu[i2] = __ldcg((const uint32_t*)&g_xw[(size_t)b * N4 + n]);
        }
    }

    __syncthreads();

    for (int ts = 0; ts < SEQ; ts++) {
        const int rp = ts & 1, wp2 = (ts + 1) & 1;
        const bool last = (ts == SEQ - 1);

        // ---- GEMM 8 x 128 x 256 (m16 rows 8-15 zero), acc split by parity ---
        float acca[2][4], accb[2][4];
#pragma unroll
        for (int i2 = 0; i2 < 2; i2++)
#pragma unroll
            for (int q = 0; q < 4; q++) { acca[i2][q] = 0.0f; accb[i2][q] = 0.0f; }

        const uint32_t* __restrict__ fh = g_hf[rp][bg];
#pragma unroll 4
        for (int ks = 0; ks < 16; ks++) {
            uint2 a2 = __ldcg((const uint2*)&fh[(ks * 32 + lane) * 2]);
            uint32_t ah[4] = {a2.x, 0u, a2.y, 0u};
            float* acc0 = (ks & 1) ? accb[0] : acca[0];
            float* acc1 = (ks & 1) ? accb[1] : acca[1];
            uint32_t b0[2], b1[2];
            *(uint2*)b0 = *(const uint2*)&Bf[((ks * 16 + 2 * w) * 32 + lane) * 2];
            *(uint2*)b1 = *(const uint2*)&Bf[((ks * 16 + 2 * w + 1) * 32 + lane) * 2];
            mmaf16(acc0, ah, b0);
            mmaf16(acc1, ah, b1);
        }

        // ---- nonlinearities -> g_s (rows 0-7 only: c0,c1) ----
#pragma unroll
        for (int i2 = 0; i2 < 2; i2++) {
            int cc = (2 * w + i2) * 8 + (lane & 3) * 2;
            int row = lane >> 2;
            float2 xv = __half22float2(*(const __half2*)&xwu[i2]);
            float z0 = acca[i2][0] + accb[i2][0] + xv.x;
            float z1 = acca[i2][1] + accb[i2][1] + xv.y;
            float q0 = sigmoidf_(__sinf(z0 * thv[i2][0]) * scv[i2][0]);
            float q1 = sigmoidf_(__sinf(z1 * thv[i2][1]) * scv[i2][1]);
            g_s[row * 132 + cc]     = va * sigmoidf_(vb * q0) + vc;
            g_s[row * 132 + cc + 1] = va * sigmoidf_(vb * q1) + vc;
        }
        __syncthreads();

        // ---- state update + h frag store (skip store on last step) ----
        float fv = g_s[b_l * 132 +       jj];
        float iv = g_s[b_l * 132 +  32 + jj];
        float uv = g_s[b_l * 132 +  64 + jj];
        float ov = g_s[b_l * 132 +  96 + jj];
        float ccv = fv * c_reg + iv * uv;
        c_reg = ccv;
        float h = ov * tanhf_fast(ccv);

        // pack (jj even, jj odd) fp16 pair; even lane stores the word
        {
            uint32_t mine = (uint32_t)__half_as_ushort(__float2half(h));
            uint32_t peer = __shfl_xor_sync(0xffffffffu, mine, 1);
            if (!last && !(t & 1)) {
                int j = j0 + jj;
                int ks = j >> 4, kk = j & 15;
                int lp = b_l * 4 + ((kk & 7) >> 1);
                int rg = kk >> 3;
                int fi = (ks * 32 + lp) * 2 + rg;
                g_hf[wp2][bg][fi] = mine | (peer << 16);
            }
        }

        if (!last) {
            // prefetch xw for ts+1 (hides under barrier)
            int b = bg * 8 + (lane >> 2);
#pragma unroll
            for (int i2 = 0; i2 < 2; i2++) {
                int cc = (2 * w + i2) * 8 + (lane & 3) * 2;
                int n = gate * 256 + j0 + (cc & 31);
                xwu[i2] = __ldcg((const uint32_t*)
                    &g_xw[((size_t)(ts + 1) * BATCH + b) * N4 + n]);
            }
            // release/acquire ordering for the gmem frag exchange
            asm volatile("barrier.cluster.arrive.aligned;" ::: "memory");
            asm volatile("barrier.cluster.wait.aligned;" ::: "memory");
        }

        // ---- out stores (off the recurrence critical path) ----
        {
            int b = bg * 8 + b_l;
            int j = j0 + jj;
            out[((size_t)ts * BATCH + b) * HID + j] = h;
            if (last) {
                size_t sidx = (size_t)b * HID + j;
                out[OUT_SEQ_ELEMS + sidx] = h;
                out[OUT_SEQ_ELEMS + (size_t)BATCH * HID + sidx] = ccv;
            }
        }
    }
}

// ---------------------------------------------------------------------------
extern "C" void kernel_launch(void* const* d_in, const int* in_sizes, int n_in,
                              void* d_out, int out_size)
{
    (void)in_sizes; (void)n_in; (void)out_size;
    const float* inputs = (const float*)d_in[0];
    const float* h0  = (const float*)d_in[1];
    const float* c0  = (const float*)d_in[2];
    const float* Wf  = (const float*)d_in[3];
    const float* bf  = (const float*)d_in[4];
    const float* thf = (const float*)d_in[5];
    const float* scf = (const float*)d_in[6];
    const float* Wi  = (const float*)d_in[7];
    const float* bi  = (const float*)d_in[8];
    const float* thi = (const float*)d_in[9];
    const float* sci = (const float*)d_in[10];
    const float* Wu  = (const float*)d_in[11];
    const float* bu  = (const float*)d_in[12];
    const float* thu = (const float*)d_in[13];
    const float* scu = (const float*)d_in[14];
    const float* Wo  = (const float*)d_in[15];
    const float* bo  = (const float*)d_in[16];
    const float* tho = (const float*)d_in[17];
    const float* sco = (const float*)d_in[18];
    float* out = (float*)d_out;

    // fused conversions (X A-frags + W B-frags + h0 frags) in one launch
    conv_all<<<4384, 256>>>(inputs, Wf, Wi, Wu, Wo, h0);

    dim3 g1(8, GM_M / 128);
    xw_mma<<<g1, 256>>>(bf, bi, bu, bo);

    const int smem2 = 16384 * 4 + 8 * 132 * 4;   // 65536 + 4224 = 69760
    cudaFuncSetAttribute(qlstm_steps, cudaFuncAttributeMaxDynamicSharedMemorySize, smem2);
    qlstm_steps<<<256, 256, smem2>>>(c0, Wf, Wi, Wu, Wo,
                                     thf, scf, thi, sci, thu, scu, tho, sco,
                                     out);
}

// round 17
// speedup vs baseline: 2.3745x; 1.0817x over previous
#include <cuda_runtime.h>
#include <cuda_fp16.h>
#include <cstdint>

#define SEQ 512
#define BATCH 256
#define HID 256
#define N4 1024
#define GM_M (SEQ * BATCH)                           // 131072 rows
#define OUT_SEQ_ELEMS ((size_t)SEQ * BATCH * HID)    // 33554432

// scratch
__device__ __half g_xw[(size_t)SEQ * BATCH * N4];                // 256 MB (fp16)

// A fragments of X (single fp16 plane): [mt 8192][ks 16][lane 32][reg 4] uint32
__device__ uint32_t g_af[(size_t)8192 * 16 * 32 * 4];            // 64 MB
// B fragments of Wx (single fp16 plane): [nf 128][ks 16][lane 32][reg 2]
__device__ uint32_t g_wf[128 * 16 * 32 * 2];                     // 512 KB

// h fragment buffers (single fp16 plane, M=8 tiles -> 2 regs/lane):
// [parity][bg 32][ (ks*32 + lp)*2 + rg ] uint32
#define FRAG_WORDS (16 * 32 * 2)
__device__ uint32_t g_hf[2][32][FRAG_WORDS];

// ---------------------------------------------------------------------------
// helpers
// ---------------------------------------------------------------------------
__device__ __forceinline__ float sigmoidf_(float x) {
    return __fdividef(1.0f, 1.0f + __expf(-x));
}
__device__ __forceinline__ float tanhf_fast(float x) {
    return 2.0f * sigmoidf_(2.0f * x) - 1.0f;
}
__device__ __forceinline__ uint32_t packh2(__half a, __half b) {
    return (uint32_t)__half_as_ushort(a) | ((uint32_t)__half_as_ushort(b) << 16);
}
__device__ __forceinline__ uint32_t pack_hi2(float a, float b) {
    return packh2(__float2half(a), __float2half(b));
}

// legacy tensor-core mma fp16 (compute_80 PTX — compiles under compute_103)
__device__ __forceinline__ void mmaf16(float* c, const uint32_t* a, const uint32_t* b) {
    asm volatile(
        "mma.sync.aligned.m16n8k16.row.col.f32.f16.f16.f32 "
        "{%0,%1,%2,%3}, {%4,%5,%6,%7}, {%8,%9}, {%0,%1,%2,%3};"
        : "+f"(c[0]), "+f"(c[1]), "+f"(c[2]), "+f"(c[3])
        : "r"(a[0]), "r"(a[1]), "r"(a[2]), "r"(a[3]), "r"(b[0]), "r"(b[1]));
}

// ---------------------------------------------------------------------------
// conv_all: one launch, block-range dispatch.
//   blocks [0, 4096)        : X fp32 -> A-fragment fp16 plane
//   blocks [4096, 4128)     : Wx fp32 -> fp16 B-fragment plane
//   blocks [4128, 4384)     : h0 -> fragment buffer parity 0 (M=8 layout)
// ---------------------------------------------------------------------------
__global__ void __launch_bounds__(256)
conv_all(const float* __restrict__ X,
         const float* __restrict__ Wf, const float* __restrict__ Wi,
         const float* __restrict__ Wu, const float* __restrict__ Wo,
         const float* __restrict__ h0) {
    const int bid = blockIdx.x;
    const int lane = threadIdx.x & 31;

    if (bid < 4096) {
        // ---- conv_x ----
        const int wg = (bid * 256 + threadIdx.x) >> 5;  // 0..32767
        const int r7 = lane >> 2;
        const int kb = (lane & 3) * 2;
#pragma unroll
        for (int q = 0; q < 4; q++) {
            int task = wg * 4 + q;                 // mt*16 + ks
            int mt = task >> 4, ks = task & 15;
            const float* base = X + (size_t)(mt * 16 + r7) * 256 + ks * 16 + kb;
            float2 v00 = *(const float2*)(base);
            float2 v01 = *(const float2*)(base + 8);
            float2 v10 = *(const float2*)(base + 8 * 256);
            float2 v11 = *(const float2*)(base + 8 * 256 + 8);
            uint4 hi;
            hi.x = pack_hi2(v00.x, v00.y);
            hi.y = pack_hi2(v10.x, v10.y);
            hi.z = pack_hi2(v01.x, v01.y);
            hi.w = pack_hi2(v11.x, v11.y);
            size_t fi = ((size_t)task * 32 + lane) * 4;
            *(uint4*)&g_af[fi] = hi;
        }
    } else if (bid < 4128) {
        // ---- conv_w ----
        const int wg = ((bid - 4096) * 256 + threadIdx.x) >> 5;  // 0..255
        const int n7 = lane >> 2;
        const int kb = (lane & 3) * 2;
#pragma unroll
        for (int q = 0; q < 8; q++) {
            int task = wg * 8 + q;                 // nf*16 + ks
            int nf = task >> 4, ks = task & 15;
            int n = nf * 8 + n7;
            int gate = n >> 8, j = n & 255;
            const float* Wp = (gate == 0) ? Wf : (gate == 1) ? Wi : (gate == 2) ? Wu : Wo;
            const float* base = Wp + (size_t)j * 512 + ks * 16 + kb;
            float2 v0 = *(const float2*)(base);
            float2 v1 = *(const float2*)(base + 8);
            uint2 hi;
            hi.x = pack_hi2(v0.x, v0.y);
            hi.y = pack_hi2(v1.x, v1.y);
            size_t fi = ((size_t)task * 32 + lane) * 2;
            *(uint2*)&g_wf[fi] = hi;
        }
    } else {
        // ---- conv_h0 (M=8 layout) ----
        int idx = (bid - 4128) * 256 + threadIdx.x;    // 65536
        int b = idx >> 8, j = idx & 255;
        float v = h0[idx];
        __half hh = __float2half(v);
        int bg = b >> 3, b_l = b & 7;
        int ks = j >> 4, kk = j & 15;
        int lp = b_l * 4 + ((kk & 7) >> 1);
        int rg = kk >> 3;
        int fi = (ks * 32 + lp) * 2 + rg;
        ((__half*)&g_hf[0][bg][fi])[kk & 1] = hh;
    }
}

// ---------------------------------------------------------------------------
// Phase 1: XW = X @ Wx^T + b. Single fp16 plane; fp16 output. (unchanged R15)
// ---------------------------------------------------------------------------
__global__ void __launch_bounds__(256, 2)
xw_mma(const float* __restrict__ bfb, const float* __restrict__ bib,
       const float* __restrict__ bub, const float* __restrict__ bob)
{
    __shared__ uint32_t Bs[16 * 16 * 32 * 2];     // 64 KB

    const int t = threadIdx.x;
    const int lane = t & 31, wid = t >> 5;
    const int bx = blockIdx.x;
    const int wm = wid & 3;
    const int wnn = wid >> 2;
    const int mtg0 = blockIdx.y * 8 + wm * 2;
    const int nfl0 = wnn * 8;

    {
        const uint4* src = (const uint4*)(g_wf + (size_t)bx * 16384);
#pragma unroll
        for (int q = 0; q < 16; q++)
            ((uint4*)Bs)[t + q * 256] = __ldg(&src[t + q * 256]);
    }

    float c[2][8][4];
#pragma unroll
    for (int i = 0; i < 2; i++)
#pragma unroll
        for (int j = 0; j < 8; j++)
#pragma unroll
            for (int q = 0; q < 4; q++) c[i][j][q] = 0.0f;

    uint32_t ah[2][2][4];
#pragma unroll
    for (int mt2 = 0; mt2 < 2; mt2++) {
        size_t fi = (((size_t)(mtg0 + mt2) * 16) * 32 + lane) * 4;
        *(uint4*)ah[0][mt2] = __ldcg((const uint4*)&g_af[fi]);
    }
    __syncthreads();

#pragma unroll 2
    for (int ks = 0; ks < 16; ks++) {
        const int cur = ks & 1, nxt = cur ^ 1;
        if (ks < 15) {
#pragma unroll
            for (int mt2 = 0; mt2 < 2; mt2++) {
                size_t fi = (((size_t)(mtg0 + mt2) * 16 + ks + 1) * 32 + lane) * 4;
                *(uint4*)ah[nxt][mt2] = __ldcg((const uint4*)&g_af[fi]);
            }
        }
#pragma unroll
        for (int nf2 = 0; nf2 < 8; nf2++) {
            uint32_t b[2];
            *(uint2*)b = *(const uint2*)&Bs[(((nfl0 + nf2) * 16 + ks) * 32 + lane) * 2];
            mmaf16(c[0][nf2], ah[cur][0], b);
            mmaf16(c[1][nf2], ah[cur][1], b);
        }
    }

    const int gate = bx >> 1;
    const float* __restrict__ bias =
        (gate == 0) ? bfb : (gate == 1) ? bib : (gate == 2) ? bub : bob;
    const int jb = (bx & 1) * 128;
    const int m0 = blockIdx.y * 128;
    const int n0 = bx * 128;
#pragma unroll
    for (int mt2 = 0; mt2 < 2; mt2++) {
#pragma unroll
        for (int nf2 = 0; nf2 < 8; nf2++) {
            int row0 = wm * 32 + mt2 * 16 + (lane >> 2);
            int col0 = wnn * 64 + nf2 * 8 + (lane & 3) * 2;
            float b0 = __ldg(&bias[jb + col0]);
            float b1 = __ldg(&bias[jb + col0 + 1]);
            size_t base = (size_t)(m0 + row0) * N4 + n0 + col0;
            *(uint32_t*)&g_xw[base] =
                pack_hi2(c[mt2][nf2][0] + b0, c[mt2][nf2][1] + b1);
            *(uint32_t*)&g_xw[base + 8 * N4] =
                pack_hi2(c[mt2][nf2][2] + b0, c[mt2][nf2][3] + b1);
        }
    }
}

// ---------------------------------------------------------------------------
// Phase 2: persistent, 256 CTAs x 256 thr, 32 independent clusters of 8.
// R16 structure; A-frags for the step fully preloaded (16 uint2 = 32 regs)
// so post-barrier L2 latency is paid once instead of 4 serialized waves.
// ---------------------------------------------------------------------------
__global__ void __cluster_dims__(8, 1, 1) __launch_bounds__(256, 2)
qlstm_steps(const float* __restrict__ c0,
            const float* __restrict__ Wf, const float* __restrict__ Wi,
            const float* __restrict__ Wu, const float* __restrict__ Wo,
            const float* __restrict__ thf, const float* __restrict__ scf,
            const float* __restrict__ thi, const float* __restrict__ sci,
            const float* __restrict__ thu, const float* __restrict__ scu,
            const float* __restrict__ tho, const float* __restrict__ sco,
            float* __restrict__ out)
{
    extern __shared__ char smraw[];
    uint32_t* Bf = (uint32_t*)smraw;               // 16384 words (64 KB)
    float* g_s = (float*)(Bf + 16384);             // [8][132]

    const int cid = blockIdx.x;                    // 0..255
    const int bg  = cid >> 3;                      // 0..31 (8 batches each)
    const int jt  = cid & 7;
    const int j0  = jt * 32;

    const int t = threadIdx.x;
    const int lane = t & 31, w = t >> 5;
    const int gate = w >> 1;

    // W -> fragment-major fp16 in SMEM (one-time, single plane)
    {
        const int c = t >> 1;
        const int kb = (t & 1) * 128;
        const int gg = c >> 5;
        const float* __restrict__ Wp = (gg == 0) ? Wf : (gg == 1) ? Wi
                                       : (gg == 2) ? Wu : Wo;
        const float* src = Wp + (size_t)(j0 + (c & 31)) * 512 + 256 + kb;
        const int nf = c >> 3;
        const int lp_base = (c & 7) * 4;
#pragma unroll 8
        for (int q = 0; q < 32; q++) {
            float4 v = *(const float4*)(src + q * 4);
            float f[4] = {v.x, v.y, v.z, v.w};
#pragma unroll
            for (int e = 0; e < 4; e++) {
                int k = kb + q * 4 + e;
                int ks = k >> 4, kk = k & 15;
                int lp = lp_base + ((kk & 7) >> 1);
                int rg = kk >> 3;
                int fi = ((ks * 16 + nf) * 32 + lp) * 2 + rg;
                ((__half*)&Bf[fi])[kk & 1] = __float2half(f[e]);
            }
        }
    }

    const float* __restrict__ thp = (gate == 0) ? thf : (gate == 1) ? thi
                                    : (gate == 2) ? thu : tho;
    const float* __restrict__ scp = (gate == 0) ? scf : (gate == 1) ? sci
                                    : (gate == 2) ? scu : sco;
    float thv[2][2], scv[2][2];
#pragma unroll
    for (int i2 = 0; i2 < 2; i2++) {
        int cc = (2 * w + i2) * 8 + (lane & 3) * 2;
        thv[i2][0] = thp[j0 + (cc & 31)];
        thv[i2][1] = thp[j0 + ((cc + 1) & 31)];
        scv[i2][0] = scp[j0 + (cc & 31)];
        scv[i2][1] = scp[j0 + ((cc + 1) & 31)];
    }
    const float va = (gate == 2) ? 2.0f : 1.0f;
    const float vb = (gate == 2) ? 2.0f : 1.0f;
    const float vc = (gate == 2) ? -1.0f : 0.0f;

    // one state per thread: b_l = t>>5, jj = t&31
    const int b_l = t >> 5, jj = t & 31;
    float c_reg = c0[(size_t)(bg * 8 + b_l) * 256 + j0 + jj];

    // initial xw prefetch for ts = 0 (row = lane>>2, 2 nf cols)
    uint32_t xwu[2];
    {
        int b = bg * 8 + (lane >> 2);
#pragma unroll
        for (int i2 = 0; i2 < 2; i2++) {
            int cc = (2 * w + i2) * 8 + (lane & 3) * 2;
            int n = gate * 256 + j0 + (cc & 31);
            xwu[i2] = __ldcg((const uint32_t*)&g_xw[(size_t)b * N4 + n]);
        }
    }

    __syncthreads();

    for (int ts = 0; ts < SEQ; ts++) {
        const int rp = ts & 1, wp2 = (ts + 1) & 1;
        const bool last = (ts == SEQ - 1);

        // ---- preload ALL 16 A-frags (one L2 latency wave, 32 regs) ----
        const uint32_t* __restrict__ fh = g_hf[rp][bg];
        uint2 a2[16];
#pragma unroll
        for (int ks = 0; ks < 16; ks++)
            a2[ks] = __ldcg((const uint2*)&fh[(ks * 32 + lane) * 2]);

        // ---- GEMM 8 x 128 x 256 (m16 rows 8-15 zero), acc split by parity ---
        float acca[2][4], accb[2][4];
#pragma unroll
        for (int i2 = 0; i2 < 2; i2++)
#pragma unroll
            for (int q = 0; q < 4; q++) { acca[i2][q] = 0.0f; accb[i2][q] = 0.0f; }

#pragma unroll
        for (int ks = 0; ks < 16; ks++) {
            uint32_t ah[4] = {a2[ks].x, 0u, a2[ks].y, 0u};
            float* acc0 = (ks & 1) ? accb[0] : acca[0];
            float* acc1 = (ks & 1) ? accb[1] : acca[1];
            uint32_t b0[2], b1[2];
            *(uint2*)b0 = *(const uint2*)&Bf[((ks * 16 + 2 * w) * 32 + lane) * 2];
            *(uint2*)b1 = *(const uint2*)&Bf[((ks * 16 + 2 * w + 1) * 32 + lane) * 2];
            mmaf16(acc0, ah, b0);
            mmaf16(acc1, ah, b1);
        }

        // ---- nonlinearities -> g_s (rows 0-7 only: c0,c1) ----
#pragma unroll
        for (int i2 = 0; i2 < 2; i2++) {
            int cc = (2 * w + i2) * 8 + (lane & 3) * 2;
            int row = lane >> 2;
            float2 xv = __half22float2(*(const __half2*)&xwu[i2]);
            float z0 = acca[i2][0] + accb[i2][0] + xv.x;
            float z1 = acca[i2][1] + accb[i2][1] + xv.y;
            float q0 = sigmoidf_(__sinf(z0 * thv[i2][0]) * scv[i2][0]);
            float q1 = sigmoidf_(__sinf(z1 * thv[i2][1]) * scv[i2][1]);
            g_s[row * 132 + cc]     = va * sigmoidf_(vb * q0) + vc;
            g_s[row * 132 + cc + 1] = va * sigmoidf_(vb * q1) + vc;
        }
        __syncthreads();

        // ---- state update + h frag store (skip store on last step) ----
        float fv = g_s[b_l * 132 +       jj];
        float iv = g_s[b_l * 132 +  32 + jj];
        float uv = g_s[b_l * 132 +  64 + jj];
        float ov = g_s[b_l * 132 +  96 + jj];
        float ccv = fv * c_reg + iv * uv;
        c_reg = ccv;
        float h = ov * tanhf_fast(ccv);

        // pack (jj even, jj odd) fp16 pair; even lane stores the word
        {
            uint32_t mine = (uint32_t)__half_as_ushort(__float2half(h));
            uint32_t peer = __shfl_xor_sync(0xffffffffu, mine, 1);
            if (!last && !(t & 1)) {
                int j = j0 + jj;
                int ks = j >> 4, kk = j & 15;
                int lp = b_l * 4 + ((kk & 7) >> 1);
                int rg = kk >> 3;
                int fi = (ks * 32 + lp) * 2 + rg;
                g_hf[wp2][bg][fi] = mine | (peer << 16);
            }
        }

        if (!last) {
            // prefetch xw for ts+1 (hides under barrier)
            int b = bg * 8 + (lane >> 2);
#pragma unroll
            for (int i2 = 0; i2 < 2; i2++) {
                int cc = (2 * w + i2) * 8 + (lane & 3) * 2;
                int n = gate * 256 + j0 + (cc & 31);
                xwu[i2] = __ldcg((const uint32_t*)
                    &g_xw[((size_t)(ts + 1) * BATCH + b) * N4 + n]);
            }
            // release/acquire ordering for the gmem frag exchange
            asm volatile("barrier.cluster.arrive.aligned;" ::: "memory");
            asm volatile("barrier.cluster.wait.aligned;" ::: "memory");
        }

        // ---- out stores (off the recurrence critical path) ----
        {
            int b = bg * 8 + b_l;
            int j = j0 + jj;
            out[((size_t)ts * BATCH + b) * HID + j] = h;
            if (last) {
                size_t sidx = (size_t)b * HID + j;
                out[OUT_SEQ_ELEMS + sidx] = h;
                out[OUT_SEQ_ELEMS + (size_t)BATCH * HID + sidx] = ccv;
            }
        }
    }
}

// ---------------------------------------------------------------------------
extern "C" void kernel_launch(void* const* d_in, const int* in_sizes, int n_in,
                              void* d_out, int out_size)
{
    (void)in_sizes; (void)n_in; (void)out_size;
    const float* inputs = (const float*)d_in[0];
    const float* h0  = (const float*)d_in[1];
    const float* c0  = (const float*)d_in[2];
    const float* Wf  = (const float*)d_in[3];
    const float* bf  = (const float*)d_in[4];
    const float* thf = (const float*)d_in[5];
    const float* scf = (const float*)d_in[6];
    const float* Wi  = (const float*)d_in[7];
    const float* bi  = (const float*)d_in[8];
    const float* thi = (const float*)d_in[9];
    const float* sci = (const float*)d_in[10];
    const float* Wu  = (const float*)d_in[11];
    const float* bu  = (const float*)d_in[12];
    const float* thu = (const float*)d_in[13];
    const float* scu = (const float*)d_in[14];
    const float* Wo  = (const float*)d_in[15];
    const float* bo  = (const float*)d_in[16];
    const float* tho = (const float*)d_in[17];
    const float* sco = (const float*)d_in[18];
    float* out = (float*)d_out;

    // fused conversions (X A-frags + W B-frags + h0 frags) in one launch
    conv_all<<<4384, 256>>>(inputs, Wf, Wi, Wu, Wo, h0);

    dim3 g1(8, GM_M / 128);
    xw_mma<<<g1, 256>>>(bf, bi, bu, bo);

    const int smem2 = 16384 * 4 + 8 * 132 * 4;   // 65536 + 4224 = 69760
    cudaFuncSetAttribute(qlstm_steps, cudaFuncAttributeMaxDynamicSharedMemorySize, smem2);
    qlstm_steps<<<256, 256, smem2>>>(c0, Wf, Wi, Wu, Wo,
                                     thf, scf, thi, sci, thu, scu, tho, sco,
                                     out);
}